// round 12
// baseline (speedup 1.0000x reference)
#include <cuda_runtime.h>
#include <cstdint>

#define D 256
#define Lh 64
#define Bh 2
#define Nh 10
#define NQh 50
#define Mh 1000
#define NSUP 20
#define NQRY 100
#define NTILE 120
#define PITCH 260
#define PA 68
#define TILE_ELEMS (Lh*D)

// ---------------- scratch (device globals; no allocations allowed) ----------------
__device__ float g_sN[NSUP*TILE_ELEMS];
__device__ float g_qN[NQRY*TILE_ELEMS];
__device__ float g_W1T[4*D*D];
__device__ float4 g_Wm4[16*4*32*32];              // proj_W bf16 hi/lo b-fragments
__device__ float4 g_baseF[NTILE*4*32*32];         // base = x@W0^T + b, fragment-native fp32
__device__ float g_Y1f[NTILE*TILE_ELEMS];         // scratch: Y1 = x@W1blk fp32
__device__ uint2 g_Y1sp[NTILE*256*32];            // Y1 split bf16 hi/lo, [tile][d][kpair]
__device__ uint4 g_AspH[NTILE*4*16*32];           // tile A-fragments (hi) for att GEMM
__device__ uint4 g_AspL[NTILE*4*16*32];           // tile A-fragments (lo)
__device__ uint4 g_BspS[NTILE*8*16*32];           // tile B-fragments (n=seq,k=d) for att GEMM
__device__ uint2 g_XspD[NTILE*256*32];            // tile B-fragments (n=d,k=seq) for pv GEMM
__device__ float g_pool[Mh*1024];
__device__ float g_logits[Mh];

// Shared-memory layout (floats), total 22280 floats = 89.1KB -> 2 CTAs/SM
#define SM_A    0
#define SM_ATT  (SM_A + Lh*PITCH)
#define SM_PMAX (SM_ATT + Lh*PA)
#define SM_PSUM (SM_PMAX + D)
#define SM_POOL (SM_PSUM + D)       // 512: [0..255]=max, [256..511]=mean
#define SM_RMAX (SM_POOL + 512)
#define SM_RSUM (SM_RMAX + 64)
#define SM_CMAX (SM_RSUM + 64)
#define SM_CSUM (SM_CMAX + 64)
#define SM_RED  (SM_CSUM + 64)
#define SM_TOTAL (SM_RED + 8)
#define SMEM_PAIR_BYTES (SM_TOTAL*4)
#define SMEM_BASE_BYTES (Lh*PITCH*4)

// ---------------- bf16 split helpers ----------------
__device__ __forceinline__ unsigned pack2(float x0, float x1){
    unsigned r; asm("cvt.rn.bf16x2.f32 %0, %1, %2;" : "=r"(r) : "f"(x1), "f"(x0)); return r;
}
__device__ __forceinline__ void split2(float x0, float x1, unsigned &h, unsigned &l){
    h = pack2(x0, x1);
    float h0 = __uint_as_float(h << 16);
    float h1 = __uint_as_float(h & 0xffff0000u);
    l = pack2(x0 - h0, x1 - h1);
}
__device__ __forceinline__ void mmab(float* c, const unsigned* a, const unsigned* b){
    asm volatile("mma.sync.aligned.m16n8k16.row.col.f32.bf16.bf16.f32 "
        "{%0,%1,%2,%3}, {%4,%5,%6,%7}, {%8,%9}, {%0,%1,%2,%3};\n"
        : "+f"(c[0]), "+f"(c[1]), "+f"(c[2]), "+f"(c[3])
        : "r"(a[0]), "r"(a[1]), "r"(a[2]), "r"(a[3]), "r"(b[0]), "r"(b[1]));
}
__device__ __forceinline__ void mma3(float* c, const unsigned* ah, const unsigned* al,
                                     const unsigned* bh, const unsigned* bl){
    mmab(c, ah, bh); mmab(c, ah, bl); mmab(c, al, bh);
}

__device__ __forceinline__ float mishf(float x){
    if (x > 20.0f) return x;
    float u = __expf(x);
    float v = u*u + 2.0f*u;
    return x * v / (v + 2.0f);
}

__device__ __forceinline__ float blockSum256(float v, float* red, int t){
    #pragma unroll
    for (int o = 16; o > 0; o >>= 1) v += __shfl_xor_sync(0xffffffffu, v, o);
    if ((t & 31) == 0) red[t >> 5] = v;
    __syncthreads();
    float s = red[0]+red[1]+red[2]+red[3]+red[4]+red[5]+red[6]+red[7];
    __syncthreads();
    return s;
}

// ---------------- kernel A: row LayerNorm ----------------
__global__ void k_ln(const float* __restrict__ sup, const float* __restrict__ qry,
                     const float* __restrict__ gg, const float* __restrict__ bb){
    __shared__ float rs[8], rq[8];
    int r = blockIdx.x, t = threadIdx.x;
    const float* src; float* dst;
    const int nsr = NSUP*Lh;
    if (r < nsr){ src = sup + (size_t)r*D; dst = g_sN + (size_t)r*D; }
    else        { src = qry + (size_t)(r-nsr)*D; dst = g_qN + (size_t)(r-nsr)*D; }
    float x = src[t];
    float s = x, q = x*x;
    #pragma unroll
    for (int o = 16; o > 0; o >>= 1){
        s += __shfl_xor_sync(0xffffffffu, s, o);
        q += __shfl_xor_sync(0xffffffffu, q, o);
    }
    if ((t & 31) == 0){ rs[t>>5] = s; rq[t>>5] = q; }
    __syncthreads();
    float S = 0.f, Q2 = 0.f;
    #pragma unroll
    for (int w = 0; w < 8; w++){ S += rs[w]; Q2 += rq[w]; }
    float mu  = S  * (1.0f/D);
    float var = Q2 * (1.0f/D) - mu*mu;
    float inv = rsqrtf(var + 1e-5f);
    dst[t] = (x - mu)*inv*gg[t] + bb[t];
}

// ---------------- kernel B: transpose W1 ----------------
__global__ void k_transposeW1(const float* __restrict__ W){
    int c = blockIdx.x, j = threadIdx.x;
    g_W1T[c*D + j] = W[(size_t)j*1024 + c];
}

// ---------------- kernel B2: proj_W -> bf16 hi/lo b-fragments ----------------
__global__ void k_prepw(const float* __restrict__ pw){
    int idx = blockIdx.x*256 + threadIdx.x;
    int lane = idx & 31;
    int jt   = (idx >> 5) & 31;
    int w    = (idx >> 10) & 3;
    int kb   = idx >> 12;
    int tig = lane & 3, gid = lane >> 2;
    int j = jt*8 + gid;
    int cblk = (w == 3) ? 0 : (w + 1);
    size_t base = (size_t)j*1024 + cblk*256 + kb*16 + 2*tig;
    unsigned bh0, bl0, bh1, bl1;
    split2(pw[base],     pw[base + 1], bh0, bl0);
    split2(pw[base + 8], pw[base + 9], bh1, bl1);
    g_Wm4[idx] = make_float4(__uint_as_float(bh0), __uint_as_float(bh1),
                             __uint_as_float(bl0), __uint_as_float(bl1));
}

// ---------------- prep: per-tile A-fragments for att GEMM ----------------
__global__ void k_prepA(){
    int idx = blockIdx.x*256 + threadIdx.x;
    int lane = idx & 31;
    int kb   = (idx >> 5) & 15;
    int ma   = (idx >> 9) & 3;
    int tile = idx >> 11;
    const float* src = (tile < NSUP) ? (g_sN + (size_t)tile*TILE_ELEMS)
                                     : (g_qN + (size_t)(tile-NSUP)*TILE_ELEMS);
    int gid = lane >> 2, tig = lane & 3;
    unsigned h[4], l[4];
    #pragma unroll
    for (int p = 0; p < 4; p++){
        int row = ma*16 + gid + (p & 1)*8;
        int col = kb*16 + 2*tig + (p >> 1)*8;
        split2(src[row*D + col], src[row*D + col + 1], h[p], l[p]);
    }
    g_AspH[idx] = make_uint4(h[0], h[1], h[2], h[3]);
    g_AspL[idx] = make_uint4(l[0], l[1], l[2], l[3]);
}

// ---------------- prep: per-tile B-fragments (n=seq,k=d) for att GEMM ----------------
__global__ void k_prepB(){
    int idx = blockIdx.x*256 + threadIdx.x;
    int lane = idx & 31;
    int kb   = (idx >> 5) & 15;
    int n8   = (idx >> 9) & 7;
    int tile = idx >> 12;
    const float* src = (tile < NSUP) ? (g_sN + (size_t)tile*TILE_ELEMS)
                                     : (g_qN + (size_t)(tile-NSUP)*TILE_ELEMS);
    int gid = lane >> 2, tig = lane & 3;
    int row = n8*8 + gid;
    int col = kb*16 + 2*tig;
    unsigned bh0, bl0, bh1, bl1;
    split2(src[row*D + col],     src[row*D + col + 1], bh0, bl0);
    split2(src[row*D + col + 8], src[row*D + col + 9], bh1, bl1);
    g_BspS[idx] = make_uint4(bh0, bh1, bl0, bl1);
}

// ---------------- prep: per-tile B-fragments (n=d,k=seq) for pv GEMM ----------------
__global__ void k_prepXD(){
    int idx = blockIdx.x*256 + threadIdx.x;
    int kp = idx & 31;
    int d  = (idx >> 5) & 255;
    int tile = idx >> 13;
    const float* src = (tile < NSUP) ? (g_sN + (size_t)tile*TILE_ELEMS)
                                     : (g_qN + (size_t)(tile-NSUP)*TILE_ELEMS);
    unsigned h, l;
    split2(src[(2*kp)*D + d], src[(2*kp + 1)*D + d], h, l);
    g_XspD[idx] = make_uint2(h, l);
}

// ---------------- kernel C: per-tile base (fragment layout) + Y1 = x@W1blk ----------------
__global__ void __launch_bounds__(256,1) k_base(const float* __restrict__ pb){
    extern __shared__ float smx[];
    int tile = blockIdx.x, t = threadIdx.x;
    const float* src = (tile < NSUP) ? (g_sN + (size_t)tile*TILE_ELEMS)
                                     : (g_qN + (size_t)(tile-NSUP)*TILE_ELEMS);
    for (int idx = t; idx < TILE_ELEMS; idx += 256){
        int row = idx >> 8, col = idx & 255;
        smx[row*PITCH + col] = src[idx];
    }
    __syncthreads();

    const int lane = t & 31, warp = t >> 5;
    const int gid = lane >> 2, tig = lane & 3;
    const int wm = warp >> 2, wn = warp & 3;

    // pass 1: base = x @ W0^T + b
    {
        float c[2][8][4];
        #pragma unroll
        for (int nt = 0; nt < 8; nt++){
            int col = wn*64 + nt*8 + 2*tig;
            float b0 = pb[col], b1 = pb[col+1];
            #pragma unroll
            for (int mt = 0; mt < 2; mt++){
                c[mt][nt][0] = b0; c[mt][nt][1] = b1;
                c[mt][nt][2] = b0; c[mt][nt][3] = b1;
            }
        }
        for (int kb = 0; kb < 16; kb++){
            unsigned ah[2][4], al[2][4];
            #pragma unroll
            for (int mt = 0; mt < 2; mt++){
                int r0 = wm*32 + mt*16 + gid;
                int c0 = kb*16 + 2*tig;
                #pragma unroll
                for (int p = 0; p < 4; p++){
                    float2 x2 = *(const float2*)(smx + (r0 + (p & 1)*8)*PITCH + c0 + (p >> 1)*8);
                    split2(x2.x, x2.y, ah[mt][p], al[mt][p]);
                }
            }
            #pragma unroll
            for (int nt = 0; nt < 8; nt++){
                float4 wv = __ldg(&g_Wm4[((kb*4 + 3)*32 + wn*8 + nt)*32 + lane]);
                unsigned bh[2] = { __float_as_uint(wv.x), __float_as_uint(wv.y) };
                unsigned bl[2] = { __float_as_uint(wv.z), __float_as_uint(wv.w) };
                mma3(c[0][nt], ah[0], al[0], bh, bl);
                mma3(c[1][nt], ah[1], al[1], bh, bl);
            }
        }
        #pragma unroll
        for (int mt = 0; mt < 2; mt++){
            int r16 = wm*2 + mt;
            #pragma unroll
            for (int nt = 0; nt < 8; nt++){
                int j8 = wn*8 + nt;
                g_baseF[((tile*4 + r16)*32 + j8)*32 + lane] =
                    make_float4(c[mt][nt][0], c[mt][nt][1], c[mt][nt][2], c[mt][nt][3]);
            }
        }
    }

    // pass 2: Y1 = x @ W1blk^T
    {
        float c[2][8][4];
        #pragma unroll
        for (int mt = 0; mt < 2; mt++)
            #pragma unroll
            for (int nt = 0; nt < 8; nt++)
                #pragma unroll
                for (int i = 0; i < 4; i++) c[mt][nt][i] = 0.f;
        for (int kb = 0; kb < 16; kb++){
            unsigned ah[2][4], al[2][4];
            #pragma unroll
            for (int mt = 0; mt < 2; mt++){
                int r0 = wm*32 + mt*16 + gid;
                int c0 = kb*16 + 2*tig;
                #pragma unroll
                for (int p = 0; p < 4; p++){
                    float2 x2 = *(const float2*)(smx + (r0 + (p & 1)*8)*PITCH + c0 + (p >> 1)*8);
                    split2(x2.x, x2.y, ah[mt][p], al[mt][p]);
                }
            }
            #pragma unroll
            for (int nt = 0; nt < 8; nt++){
                float4 wv = __ldg(&g_Wm4[((kb*4 + 0)*32 + wn*8 + nt)*32 + lane]);
                unsigned bh[2] = { __float_as_uint(wv.x), __float_as_uint(wv.y) };
                unsigned bl[2] = { __float_as_uint(wv.z), __float_as_uint(wv.w) };
                mma3(c[0][nt], ah[0], al[0], bh, bl);
                mma3(c[1][nt], ah[1], al[1], bh, bl);
            }
        }
        float* dst = g_Y1f + (size_t)tile*TILE_ELEMS;
        #pragma unroll
        for (int mt = 0; mt < 2; mt++){
            int r0 = wm*32 + mt*16 + gid;
            #pragma unroll
            for (int nt = 0; nt < 8; nt++){
                int col = wn*64 + nt*8 + 2*tig;
                *(float2*)(dst + r0*D + col)     = make_float2(c[mt][nt][0], c[mt][nt][1]);
                *(float2*)(dst + (r0+8)*D + col) = make_float2(c[mt][nt][2], c[mt][nt][3]);
            }
        }
    }
}

// ---------------- kernel C2: split Y1 -> g_Y1sp[tile][d][kpair] ----------------
__global__ void k_prepY1(){
    int idx = blockIdx.x*256 + threadIdx.x;
    int tile = idx >> 13;
    int rem  = idx & 8191;
    int d  = rem >> 5;
    int kp = rem & 31;
    const float* Y = g_Y1f + (size_t)tile*TILE_ELEMS;
    float y0 = Y[(2*kp)*D + d];
    float y1 = Y[(2*kp+1)*D + d];
    unsigned h, l; split2(y0, y1, h, l);
    g_Y1sp[idx] = make_uint2(h, l);
}

// ---------------- pv (256 threads, 2 d-passes): a_t = scal * (A @ X) ----------------
__device__ __forceinline__ void pv256(const float* __restrict__ attm, int transA,
                                      const uint2* __restrict__ xsp,
                                      const float* __restrict__ rscale,
                                      float* __restrict__ out, int t){
    const int lane = t & 31, warp = t >> 5;
    const int gid = lane >> 2, tig = lane & 3;
    const int wm = warp >> 2, wn = warp & 3;
    #pragma unroll 1
    for (int h = 0; h < 2; h++){
        float c[2][4][4];
        #pragma unroll
        for (int mt = 0; mt < 2; mt++)
            #pragma unroll
            for (int nt = 0; nt < 4; nt++)
                #pragma unroll
                for (int i = 0; i < 4; i++) c[mt][nt][i] = 0.f;
        for (int kb = 0; kb < 4; kb++){
            unsigned ah[2][4], al[2][4];
            #pragma unroll
            for (int mt = 0; mt < 2; mt++)
                #pragma unroll
                for (int p = 0; p < 4; p++){
                    int rr = wm*32 + mt*16 + gid + (p & 1)*8;
                    int cc = kb*16 + 2*tig + (p >> 1)*8;
                    float v0, v1;
                    if (transA){ v0 = attm[cc*PA + rr]; v1 = attm[(cc+1)*PA + rr]; }
                    else { float2 v = *(const float2*)(attm + rr*PA + cc); v0 = v.x; v1 = v.y; }
                    split2(v0, v1, ah[mt][p], al[mt][p]);
                }
            #pragma unroll
            for (int nt = 0; nt < 4; nt++){
                int d0 = h*128 + wn*32 + nt*8 + gid;
                int kp = kb*8 + tig;
                uint2 xu0 = __ldg(&xsp[d0*32 + kp]);
                uint2 xu1 = __ldg(&xsp[d0*32 + kp + 4]);
                unsigned bh[2] = { xu0.x, xu1.x };
                unsigned bl[2] = { xu0.y, xu1.y };
                mma3(c[0][nt], ah[0], al[0], bh, bl);
                mma3(c[1][nt], ah[1], al[1], bh, bl);
            }
        }
        #pragma unroll
        for (int mt = 0; mt < 2; mt++){
            int r0 = wm*32 + mt*16 + gid;
            float s0 = rscale ? rscale[r0]   : 1.0f;
            float s1 = rscale ? rscale[r0+8] : 1.0f;
            #pragma unroll
            for (int nt = 0; nt < 4; nt++){
                int col = h*128 + wn*32 + nt*8 + 2*tig;
                *(float2*)(out + r0*PITCH + col)     = make_float2(c[mt][nt][0]*s0, c[mt][nt][1]*s0);
                *(float2*)(out + (r0+8)*PITCH + col) = make_float2(c[mt][nt][2]*s1, c[mt][nt][3]*s1);
            }
        }
    }
}

// ---------------- proj (256 threads, 2 j-passes): c2 + base + 2-feature mma + pool --------
__device__ __forceinline__ void proj256(const float* __restrict__ attm, int transA,
    const uint2* __restrict__ ysp, const float* __restrict__ scal,
    const float4* __restrict__ basef, const float* __restrict__ xg,
    const float* __restrict__ a_t, float* pmax, float* psum, float* pool, int t)
{
    const int lane = t & 31, warp = t >> 5;
    const int gid = lane >> 2, tig = lane & 3;
    const int wm = warp >> 2, wn = warp & 3;

    #pragma unroll 1
    for (int h = 0; h < 2; h++){
        float c[2][4][4];
        #pragma unroll
        for (int mt = 0; mt < 2; mt++)
            #pragma unroll
            for (int nt = 0; nt < 4; nt++)
                #pragma unroll
                for (int i = 0; i < 4; i++) c[mt][nt][i] = 0.f;

        // c2 = A @ Y1 for this pass's 32 j-columns
        for (int kb = 0; kb < 4; kb++){
            unsigned ah[2][4], al[2][4];
            #pragma unroll
            for (int mt = 0; mt < 2; mt++)
                #pragma unroll
                for (int p = 0; p < 4; p++){
                    int rr = wm*32 + mt*16 + gid + (p & 1)*8;
                    int cc = kb*16 + 2*tig + (p >> 1)*8;
                    float v0, v1;
                    if (transA){ v0 = attm[cc*PA + rr]; v1 = attm[(cc+1)*PA + rr]; }
                    else { float2 v = *(const float2*)(attm + rr*PA + cc); v0 = v.x; v1 = v.y; }
                    split2(v0, v1, ah[mt][p], al[mt][p]);
                }
            #pragma unroll
            for (int nt = 0; nt < 4; nt++){
                int d0 = wn*64 + h*32 + nt*8 + gid;
                int kp = kb*8 + tig;
                uint2 yu0 = __ldg(&ysp[d0*32 + kp]);
                uint2 yu1 = __ldg(&ysp[d0*32 + kp + 4]);
                unsigned bh[2] = { yu0.x, yu1.x };
                unsigned bl[2] = { yu0.y, yu1.y };
                mma3(c[0][nt], ah[0], al[0], bh, bl);
                mma3(c[1][nt], ah[1], al[1], bh, bl);
            }
        }
        // scale c2 rows, add base
        {
            float s0 = 1.f, s0b = 1.f, s1 = 1.f, s1b = 1.f;
            if (scal){
                s0  = scal[wm*32 + gid];      s0b = scal[wm*32 + gid + 8];
                s1  = scal[wm*32 + 16 + gid]; s1b = scal[wm*32 + 24 + gid];
            }
            #pragma unroll
            for (int mt = 0; mt < 2; mt++){
                float sa = (mt == 0) ? s0  : s1;
                float sb = (mt == 0) ? s0b : s1b;
                #pragma unroll
                for (int nt = 0; nt < 4; nt++){
                    float4 bv = __ldg(&basef[((wm*2 + mt)*32 + wn*8 + h*4 + nt)*32 + lane]);
                    c[mt][nt][0] = bv.x + c[mt][nt][0]*sa;
                    c[mt][nt][1] = bv.y + c[mt][nt][1]*sa;
                    c[mt][nt][2] = bv.z + c[mt][nt][2]*sb;
                    c[mt][nt][3] = bv.w + c[mt][nt][3]*sb;
                }
            }
        }

        // main proj loop: features |x-a| and x*a
        for (int kb = 0; kb < 16; kb++){
            float2 xv[2][4], av[2][4];
            #pragma unroll
            for (int mt = 0; mt < 2; mt++){
                int r0 = wm*32 + mt*16 + gid;
                int c0 = kb*16 + 2*tig;
                #pragma unroll
                for (int p = 0; p < 4; p++){
                    int rr = r0 + (p & 1)*8;
                    int cc = c0 + (p >> 1)*8;
                    xv[mt][p] = __ldg((const float2*)(xg + rr*D + cc));
                    av[mt][p] = *(const float2*)(a_t + rr*PITCH + cc);
                }
            }
            {
                unsigned ah[2][4], al[2][4];
                #pragma unroll
                for (int mt = 0; mt < 2; mt++)
                    #pragma unroll
                    for (int p = 0; p < 4; p++)
                        split2(fabsf(xv[mt][p].x - av[mt][p].x),
                               fabsf(xv[mt][p].y - av[mt][p].y), ah[mt][p], al[mt][p]);
                #pragma unroll
                for (int nt = 0; nt < 4; nt++){
                    float4 wv = __ldg(&g_Wm4[((kb*4 + 1)*32 + wn*8 + h*4 + nt)*32 + lane]);
                    unsigned bh[2] = { __float_as_uint(wv.x), __float_as_uint(wv.y) };
                    unsigned bl[2] = { __float_as_uint(wv.z), __float_as_uint(wv.w) };
                    mma3(c[0][nt], ah[0], al[0], bh, bl);
                    mma3(c[1][nt], ah[1], al[1], bh, bl);
                }
            }
            {
                unsigned ah[2][4], al[2][4];
                #pragma unroll
                for (int mt = 0; mt < 2; mt++)
                    #pragma unroll
                    for (int p = 0; p < 4; p++)
                        split2(xv[mt][p].x * av[mt][p].x,
                               xv[mt][p].y * av[mt][p].y, ah[mt][p], al[mt][p]);
                #pragma unroll
                for (int nt = 0; nt < 4; nt++){
                    float4 wv = __ldg(&g_Wm4[((kb*4 + 2)*32 + wn*8 + h*4 + nt)*32 + lane]);
                    unsigned bh[2] = { __float_as_uint(wv.x), __float_as_uint(wv.y) };
                    unsigned bl[2] = { __float_as_uint(wv.z), __float_as_uint(wv.w) };
                    mma3(c[0][nt], ah[0], al[0], bh, bl);
                    mma3(c[1][nt], ah[1], al[1], bh, bl);
                }
            }
        }

        // mish + pooling partials for this pass's 32 j-columns
        float mymax[4][2], mysum[4][2];
        #pragma unroll
        for (int nt = 0; nt < 4; nt++){
            #pragma unroll
            for (int e = 0; e < 2; e++){
                float v00 = mishf(c[0][nt][e]);
                float v01 = mishf(c[0][nt][2+e]);
                float v10 = mishf(c[1][nt][e]);
                float v11 = mishf(c[1][nt][2+e]);
                float mx = fmaxf(fmaxf(v00, v01), fmaxf(v10, v11));
                float smv = (v00 + v01) + (v10 + v11);
                #pragma unroll
                for (int off = 4; off < 32; off <<= 1){
                    mx = fmaxf(mx, __shfl_xor_sync(0xffffffffu, mx, off));
                    smv += __shfl_xor_sync(0xffffffffu, smv, off);
                }
                mymax[nt][e] = mx; mysum[nt][e] = smv;
            }
        }
        if (wm == 1 && gid == 0){
            #pragma unroll
            for (int nt = 0; nt < 4; nt++)
                #pragma unroll
                for (int e = 0; e < 2; e++){
                    int j = wn*64 + h*32 + nt*8 + 2*tig + e;
                    pmax[j] = mymax[nt][e]; psum[j] = mysum[nt][e];
                }
        }
        __syncthreads();
        if (wm == 0 && gid == 0){
            #pragma unroll
            for (int nt = 0; nt < 4; nt++)
                #pragma unroll
                for (int e = 0; e < 2; e++){
                    int j = wn*64 + h*32 + nt*8 + 2*tig + e;
                    pool[j]       = fmaxf(mymax[nt][e], pmax[j]);
                    pool[256 + j] = (mysum[nt][e] + psum[j]) * (1.0f/(float)Lh);
                }
        }
        __syncthreads();
    }
}

// ---------------- kernel D: one CTA per pair (256 threads, 2 CTAs/SM) ----------------
__global__ void __launch_bounds__(256, 2) k_pair(
    const float* __restrict__ ln2g, const float* __restrict__ ln2b)
{
    extern __shared__ float sm[];
    float* a_t  = sm + SM_A;
    float* att  = sm + SM_ATT;
    float* pmax = sm + SM_PMAX;
    float* psum = sm + SM_PSUM;
    float* pool = sm + SM_POOL;
    float* rmax = sm + SM_RMAX;
    float* rsum = sm + SM_RSUM;
    float* cmax = sm + SM_CMAX;
    float* csum = sm + SM_CSUM;
    float* red  = sm + SM_RED;

    const int m = blockIdx.x;
    const int b = m / (NQh*Nh);
    const int rem = m % (NQh*Nh);
    const int iq = rem / Nh;
    const int n  = rem % Nh;
    const int sIdx = b*Nh + n;
    const int qIdx = b*NQh + iq;
    const int qTile = NSUP + qIdx;
    const int t = threadIdx.x;
    const int lane = t & 31, warp = t >> 5;
    const int gid = lane >> 2, tig = lane & 3;

    // -------- att GEMM (8 warps: 4x2 grid; 16 rows x 32 cols per warp) --------
    {
        const int wma = warp >> 1, wna = warp & 1;
        float ca[4][4];
        #pragma unroll
        for (int nt = 0; nt < 4; nt++)
            #pragma unroll
            for (int i = 0; i < 4; i++) ca[nt][i] = 0.f;
        const uint4* aspH = g_AspH + ((size_t)sIdx*4 + wma)*16*32;
        const uint4* aspL = g_AspL + ((size_t)sIdx*4 + wma)*16*32;
        for (int kb = 0; kb < 16; kb++){
            uint4 AH = __ldg(&aspH[kb*32 + lane]);
            uint4 AL = __ldg(&aspL[kb*32 + lane]);
            unsigned ah[4] = { AH.x, AH.y, AH.z, AH.w };
            unsigned al[4] = { AL.x, AL.y, AL.z, AL.w };
            #pragma unroll
            for (int nt = 0; nt < 4; nt++){
                int n8 = wna*4 + nt;
                uint4 B = __ldg(&g_BspS[(((size_t)qTile*8 + n8)*16 + kb)*32 + lane]);
                unsigned bh[2] = { B.x, B.y };
                unsigned bl[2] = { B.z, B.w };
                mma3(ca[nt], ah, al, bh, bl);
            }
        }
        #pragma unroll
        for (int nt = 0; nt < 4; nt++){
            int r0 = wma*16 + gid;
            int col = (wna*4 + nt)*8 + 2*tig;
            *(float2*)(att + r0*PA + col)     = make_float2(ca[nt][0], ca[nt][1]);
            *(float2*)(att + (r0+8)*PA + col) = make_float2(ca[nt][2], ca[nt][3]);
        }
    }
    __syncthreads();

    // -------- row & column maxima (4 threads each) --------
    {
        int row = t >> 2, sub = t & 3;
        const float* rp = att + row*PA + sub*16;
        float mx = -3.4e38f;
        #pragma unroll
        for (int i = 0; i < 16; i++) mx = fmaxf(mx, rp[i]);
        mx = fmaxf(mx, __shfl_xor_sync(0xffffffffu, mx, 1));
        mx = fmaxf(mx, __shfl_xor_sync(0xffffffffu, mx, 2));
        if (sub == 0) rmax[row] = mx;
    }
    {
        int col = t >> 2, sub = t & 3;
        float mx = -3.4e38f;
        #pragma unroll
        for (int i = 0; i < 16; i++) mx = fmaxf(mx, att[(sub*16 + i)*PA + col]);
        mx = fmaxf(mx, __shfl_xor_sync(0xffffffffu, mx, 1));
        mx = fmaxf(mx, __shfl_xor_sync(0xffffffffu, mx, 2));
        if (sub == 0) cmax[col] = mx;
    }
    __syncthreads();

    // -------- att := E = exp(att - rmax[l]) --------
    {
        const int k = t & 63, l0 = t >> 6;   // 0..3
        #pragma unroll
        for (int i = 0; i < 16; i++){
            int l = l0 + 4*i;
            att[l*PA + k] = __expf(att[l*PA + k] - rmax[l]);
        }
    }
    __syncthreads();

    // -------- row sums + column sums (rebased to cmax) --------
    {
        int row = t >> 2, sub = t & 3;
        const float* rp = att + row*PA + sub*16;
        float s = 0.f;
        #pragma unroll
        for (int i = 0; i < 16; i++) s += rp[i];
        s += __shfl_xor_sync(0xffffffffu, s, 1);
        s += __shfl_xor_sync(0xffffffffu, s, 2);
        if (sub == 0) rsum[row] = 1.0f / s;
    }
    {
        int col = t >> 2, sub = t & 3;
        float cm = cmax[col];
        float s = 0.f;
        #pragma unroll
        for (int i = 0; i < 16; i++){
            int l = sub*16 + i;
            float hh = __expf(0.5f*(rmax[l] - cm));
            s += att[l*PA + col] * hh * hh;
        }
        s += __shfl_xor_sync(0xffffffffu, s, 1);
        s += __shfl_xor_sync(0xffffffffu, s, 2);
        if (sub == 0) csum[col] = 1.0f / s;
    }
    __syncthreads();

    // ======== PHASE S ========
    pv256(att, 0, g_XspD + (size_t)qTile*8192, rsum, a_t, t);
    __syncthreads();
    proj256(att, 0, g_Y1sp + (size_t)qTile*8192, rsum,
            g_baseF + (size_t)sIdx*4096, g_sN + (size_t)sIdx*TILE_ELEMS,
            a_t, pmax, psum, pool, t);
    // LayerNorm(512) + store s_pool -> cat[512..1023]
    {
        float v0 = pool[t], v1 = pool[t + 256];
        float S  = blockSum256(v0 + v1,       red, t);
        float SS = blockSum256(v0*v0 + v1*v1, red, t);
        float mean = S  * (1.0f/512.0f);
        float var  = SS * (1.0f/512.0f) - mean*mean;
        float inv  = rsqrtf(var + 1e-5f);
        g_pool[(size_t)m*1024 + 512 + t]       = (v0 - mean)*inv*ln2g[t]       + ln2b[t];
        g_pool[(size_t)m*1024 + 512 + 256 + t] = (v1 - mean)*inv*ln2g[256 + t] + ln2b[256 + t];
    }
    __syncthreads();

    // -------- att := P_col = exp(raw - cmax)/colsum --------
    {
        const int k = t & 63, l0 = t >> 6;
        float ci = csum[k], cm = cmax[k];
        #pragma unroll
        for (int i = 0; i < 16; i++){
            int l = l0 + 4*i;
            float hh = __expf(0.5f*(rmax[l] - cm));
            att[l*PA + k] = att[l*PA + k] * hh * hh * ci;
        }
    }
    __syncthreads();

    // ======== PHASE Q ========
    pv256(att, 1, g_XspD + (size_t)sIdx*8192, (const float*)0, a_t, t);
    __syncthreads();
    proj256(att, 1, g_Y1sp + (size_t)sIdx*8192, (const float*)0,
            g_baseF + (size_t)qTile*4096, g_qN + (size_t)qIdx*TILE_ELEMS,
            a_t, pmax, psum, pool, t);
    // LayerNorm(512) + store q_pool -> cat[0..511]
    {
        float v0 = pool[t], v1 = pool[t + 256];
        float S  = blockSum256(v0 + v1,       red, t);
        float SS = blockSum256(v0*v0 + v1*v1, red, t);
        float mean = S  * (1.0f/512.0f);
        float var  = SS * (1.0f/512.0f) - mean*mean;
        float inv  = rsqrtf(var + 1e-5f);
        g_pool[(size_t)m*1024 + t]       = (v0 - mean)*inv*ln2g[t]       + ln2b[t];
        g_pool[(size_t)m*1024 + 256 + t] = (v1 - mean)*inv*ln2g[256 + t] + ln2b[256 + t];
    }
}

// ---------------- kernel H: batched MLP head (8 pairs per block) ----------------
__global__ void __launch_bounds__(256) k_head(
    const float* __restrict__ b1v, const float* __restrict__ W2,
    const float* __restrict__ b2,  const float* __restrict__ W3,
    const float* __restrict__ b3)
{
    __shared__ float ps[8*1024];
    __shared__ float red[8][8];
    int t = threadIdx.x;
    int m0 = blockIdx.x*8;
    for (int i = t; i < 8*1024; i += 256) ps[i] = g_pool[(size_t)m0*1024 + i];
    __syncthreads();
    float acc[8];
    #pragma unroll
    for (int r = 0; r < 8; r++) acc[r] = 0.f;
    #pragma unroll 4
    for (int c = 0; c < 1024; c++){
        float w = g_W1T[c*D + t];
        #pragma unroll
        for (int r = 0; r < 8; r++) acc[r] += ps[r*1024 + c]*w;
    }
    float b1j = b1v[t], w2j = W2[t];
    #pragma unroll
    for (int r = 0; r < 8; r++){
        float part = mishf(acc[r] + b1j) * w2j;
        #pragma unroll
        for (int o = 16; o > 0; o >>= 1) part += __shfl_xor_sync(0xffffffffu, part, o);
        if ((t & 31) == 0) red[r][t >> 5] = part;
    }
    __syncthreads();
    if (t < 8){
        float tot = 0.f;
        #pragma unroll
        for (int w = 0; w < 8; w++) tot += red[t][w];
        g_logits[m0 + t] = mishf(tot + b2[0])*W3[0] + b3[0];
    }
}

// ---------------- kernel E: min-append, logits layout, argmax ----------------
__global__ void k_final(float* __restrict__ out, int out_size){
    int u = threadIdx.x;
    if (u >= Bh*NQh) return;
    float v[Nh];
    float mn = 3.4e38f;
    #pragma unroll
    for (int n2 = 0; n2 < Nh; n2++){
        v[n2] = g_logits[u*Nh + n2];
        mn = fminf(mn, v[n2]);
    }
    if (out_size >= 1100){
        float best = -3.4e38f; int bi = 0;
        #pragma unroll
        for (int n2 = 0; n2 < Nh; n2++){
            out[u*(Nh+1) + n2] = v[n2];
            if (v[n2] > best){ best = v[n2]; bi = n2; }
        }
        out[u*(Nh+1) + Nh] = mn - 1.0f;
        if (out_size >= 1200) out[Bh*NQh*(Nh+1) + u] = (float)bi;
    } else if (out_size == Bh*NQh){
        float best = -3.4e38f; int bi = 0;
        #pragma unroll
        for (int n2 = 0; n2 < Nh; n2++)
            if (v[n2] > best){ best = v[n2]; bi = n2; }
        ((int*)out)[u] = bi;
    }
}

// ---------------- launch ----------------
extern "C" void kernel_launch(void* const* d_in, const int* in_sizes, int n_in,
                              void* d_out, int out_size)
{
    const float* support = (const float*)d_in[0];
    const float* query   = (const float*)d_in[1];
    const float* ln_g    = (const float*)d_in[2];
    const float* ln_b    = (const float*)d_in[3];
    const float* ln2_g   = (const float*)d_in[4];
    const float* ln2_b   = (const float*)d_in[5];
    const float* proj_W  = (const float*)d_in[6];
    const float* proj_b  = (const float*)d_in[7];
    const float* W1      = (const float*)d_in[8];
    const float* b1      = (const float*)d_in[9];
    const float* W2      = (const float*)d_in[10];
    const float* b2      = (const float*)d_in[11];
    const float* W3      = (const float*)d_in[12];
    const float* b3      = (const float*)d_in[13];

    cudaFuncSetAttribute(k_pair, cudaFuncAttributeMaxDynamicSharedMemorySize, SMEM_PAIR_BYTES);
    cudaFuncSetAttribute(k_base, cudaFuncAttributeMaxDynamicSharedMemorySize, SMEM_BASE_BYTES);

    k_ln<<<(NSUP + NQRY)*Lh, 256>>>(support, query, ln_g, ln_b);
    k_transposeW1<<<1024, 256>>>(W1);
    k_prepw<<<256, 256>>>(proj_W);
    k_prepA<<<NTILE*8, 256>>>();
    k_prepB<<<NTILE*16, 256>>>();
    k_prepXD<<<NTILE*32, 256>>>();
    k_base<<<NTILE, 256, SMEM_BASE_BYTES>>>(proj_b);
    k_prepY1<<<NTILE*32, 256>>>();
    k_pair<<<Mh, 256, SMEM_PAIR_BYTES>>>(ln2_g, ln2_b);
    k_head<<<Mh/8, 256>>>(b1, W2, b2, W3, b3);
    k_final<<<1, 128>>>((float*)d_out, out_size);
}

// round 13
// speedup vs baseline: 1.1531x; 1.1531x over previous
#include <cuda_runtime.h>
#include <cstdint>

#define D 256
#define Lh 64
#define Bh 2
#define Nh 10
#define NQh 50
#define Mh 1000
#define NSUP 20
#define NQRY 100
#define NTILE 120
#define PITCH 260
#define PA 68
#define TILE_ELEMS (Lh*D)

// ---------------- scratch (device globals; no allocations allowed) ----------------
__device__ float g_sN[NSUP*TILE_ELEMS];
__device__ float g_qN[NQRY*TILE_ELEMS];
__device__ float4 g_Wm4[16*4*32*32];              // proj_W bf16 hi/lo b-fragments (1MB)
__device__ float4 g_baseF[NTILE*4*32*32];         // base = x@W0^T + b, fragment-native fp32
__device__ float g_Y1f[NTILE*TILE_ELEMS];         // scratch: Y1 = x@W1blk fp32
__device__ uint2 g_Y1sp[NTILE*256*32];            // Y1 split bf16 hi/lo, [tile][d][kpair]
__device__ float g_pool[Mh*1024];                 // pooled+LN'd cat vectors
__device__ float g_logits[Mh];

// Shared-memory layout (floats) for the pair kernel
#define SM_S    0
#define SM_Q    (SM_S + Lh*PITCH)
#define SM_A    (SM_Q + Lh*PITCH)
#define SM_ATT  (SM_A + Lh*PITCH)
#define SM_PMAX (SM_ATT + Lh*PA)
#define SM_PSUM (SM_PMAX + D)
#define SM_POOL (SM_PSUM + D)       // 1024: [0..511]=q_pool, [512..1023]=s_pool
#define SM_RMAX (SM_POOL + 1024)
#define SM_RSUM (SM_RMAX + 64)
#define SM_CMAX (SM_RSUM + 64)
#define SM_CSUM (SM_CMAX + 64)
#define SM_RED  (SM_CSUM + 64)
#define SM_TOTAL (SM_RED + 32)
#define SMEM_PAIR_BYTES (SM_TOTAL*4)
#define SMEM_BASE_BYTES (Lh*PITCH*4)

// ---------------- bf16 split helpers ----------------
__device__ __forceinline__ unsigned pack2(float x0, float x1){
    unsigned r; asm("cvt.rn.bf16x2.f32 %0, %1, %2;" : "=r"(r) : "f"(x1), "f"(x0)); return r;
}
__device__ __forceinline__ void split2(float x0, float x1, unsigned &h, unsigned &l){
    h = pack2(x0, x1);
    float h0 = __uint_as_float(h << 16);
    float h1 = __uint_as_float(h & 0xffff0000u);
    l = pack2(x0 - h0, x1 - h1);
}
__device__ __forceinline__ void mmab(float* c, const unsigned* a, const unsigned* b){
    asm volatile("mma.sync.aligned.m16n8k16.row.col.f32.bf16.bf16.f32 "
        "{%0,%1,%2,%3}, {%4,%5,%6,%7}, {%8,%9}, {%0,%1,%2,%3};\n"
        : "+f"(c[0]), "+f"(c[1]), "+f"(c[2]), "+f"(c[3])
        : "r"(a[0]), "r"(a[1]), "r"(a[2]), "r"(a[3]), "r"(b[0]), "r"(b[1]));
}
__device__ __forceinline__ void mma3(float* c, const unsigned* ah, const unsigned* al,
                                     const unsigned* bh, const unsigned* bl){
    mmab(c, ah, bh); mmab(c, ah, bl); mmab(c, al, bh);
}

// mish(x) = x * tanh(softplus(x)) = x * (u^2+2u)/(u^2+2u+2), u = e^x
__device__ __forceinline__ float mishf(float x){
    if (x > 20.0f) return x;
    float u = __expf(x);
    float v = u*u + 2.0f*u;
    return x * v / (v + 2.0f);
}

// block-wide sum over 512 threads (16 warps)
__device__ __forceinline__ float blockSum512(float v, float* red, int t){
    #pragma unroll
    for (int o = 16; o > 0; o >>= 1) v += __shfl_xor_sync(0xffffffffu, v, o);
    if ((t & 31) == 0) red[t >> 5] = v;
    __syncthreads();
    float s = 0.f;
    #pragma unroll
    for (int w = 0; w < 16; w++) s += red[w];
    __syncthreads();
    return s;
}

// ---------------- kernel A: row LayerNorm of support & query ----------------
__global__ void k_ln(const float* __restrict__ sup, const float* __restrict__ qry,
                     const float* __restrict__ gg, const float* __restrict__ bb){
    __shared__ float rs[8], rq[8];
    int r = blockIdx.x, t = threadIdx.x;
    const float* src; float* dst;
    const int nsr = NSUP*Lh;
    if (r < nsr){ src = sup + (size_t)r*D; dst = g_sN + (size_t)r*D; }
    else        { src = qry + (size_t)(r-nsr)*D; dst = g_qN + (size_t)(r-nsr)*D; }
    float x = src[t];
    float s = x, q = x*x;
    #pragma unroll
    for (int o = 16; o > 0; o >>= 1){
        s += __shfl_xor_sync(0xffffffffu, s, o);
        q += __shfl_xor_sync(0xffffffffu, q, o);
    }
    if ((t & 31) == 0){ rs[t>>5] = s; rq[t>>5] = q; }
    __syncthreads();
    float S = 0.f, Q2 = 0.f;
    #pragma unroll
    for (int w = 0; w < 8; w++){ S += rs[w]; Q2 += rq[w]; }
    float mu  = S  * (1.0f/D);
    float var = Q2 * (1.0f/D) - mu*mu;
    float inv = rsqrtf(var + 1e-5f);
    dst[t] = (x - mu)*inv*gg[t] + bb[t];
}

// ---------------- kernel B2: proj_W -> bf16 hi/lo b-fragments ----------------
__global__ void k_prepw(const float* __restrict__ pw){
    int idx = blockIdx.x*256 + threadIdx.x;     // 65536 total
    int lane = idx & 31;
    int jt   = (idx >> 5) & 31;
    int w    = (idx >> 10) & 3;
    int kb   = idx >> 12;
    int tig = lane & 3, gid = lane >> 2;
    int j = jt*8 + gid;
    int cblk = (w == 3) ? 0 : (w + 1);
    size_t base = (size_t)j*1024 + cblk*256 + kb*16 + 2*tig;
    unsigned bh0, bl0, bh1, bl1;
    split2(pw[base],     pw[base + 1], bh0, bl0);
    split2(pw[base + 8], pw[base + 9], bh1, bl1);
    g_Wm4[idx] = make_float4(__uint_as_float(bh0), __uint_as_float(bh1),
                             __uint_as_float(bl0), __uint_as_float(bl1));
}

// ---------------- kernel C-a: per-tile base = x @ W0^T + b (fragment layout) ----------------
__global__ void __launch_bounds__(256,2) k_base1(const float* __restrict__ pb){
    extern __shared__ float smx[];
    int tile = blockIdx.x, t = threadIdx.x;
    const float* src = (tile < NSUP) ? (g_sN + (size_t)tile*TILE_ELEMS)
                                     : (g_qN + (size_t)(tile-NSUP)*TILE_ELEMS);
    for (int idx = t; idx < TILE_ELEMS; idx += 256){
        int row = idx >> 8, col = idx & 255;
        smx[row*PITCH + col] = src[idx];
    }
    __syncthreads();

    const int lane = t & 31, warp = t >> 5;
    const int gid = lane >> 2, tig = lane & 3;
    const int wm = warp >> 2, wn = warp & 3;

    float c[2][8][4];
    #pragma unroll
    for (int nt = 0; nt < 8; nt++){
        int col = wn*64 + nt*8 + 2*tig;
        float b0 = pb[col], b1 = pb[col+1];
        #pragma unroll
        for (int mt = 0; mt < 2; mt++){
            c[mt][nt][0] = b0; c[mt][nt][1] = b1;
            c[mt][nt][2] = b0; c[mt][nt][3] = b1;
        }
    }
    for (int kb = 0; kb < 16; kb++){
        unsigned ah[2][4], al[2][4];
        #pragma unroll
        for (int mt = 0; mt < 2; mt++){
            int r0 = wm*32 + mt*16 + gid;
            int c0 = kb*16 + 2*tig;
            #pragma unroll
            for (int p = 0; p < 4; p++){
                float2 x2 = *(const float2*)(smx + (r0 + (p & 1)*8)*PITCH + c0 + (p >> 1)*8);
                split2(x2.x, x2.y, ah[mt][p], al[mt][p]);
            }
        }
        #pragma unroll
        for (int nt = 0; nt < 8; nt++){
            float4 wv = __ldg(&g_Wm4[((kb*4 + 3)*32 + wn*8 + nt)*32 + lane]);
            unsigned bh[2] = { __float_as_uint(wv.x), __float_as_uint(wv.y) };
            unsigned bl[2] = { __float_as_uint(wv.z), __float_as_uint(wv.w) };
            mma3(c[0][nt], ah[0], al[0], bh, bl);
            mma3(c[1][nt], ah[1], al[1], bh, bl);
        }
    }
    #pragma unroll
    for (int mt = 0; mt < 2; mt++){
        int r16 = wm*2 + mt;
        #pragma unroll
        for (int nt = 0; nt < 8; nt++){
            int j8 = wn*8 + nt;
            g_baseF[((tile*4 + r16)*32 + j8)*32 + lane] =
                make_float4(c[mt][nt][0], c[mt][nt][1], c[mt][nt][2], c[mt][nt][3]);
        }
    }
}

// ---------------- kernel C-b: per-tile Y1 = x @ W1blk^T (fp32 scratch) ----------------
__global__ void __launch_bounds__(256,2) k_base2(){
    extern __shared__ float smx[];
    int tile = blockIdx.x, t = threadIdx.x;
    const float* src = (tile < NSUP) ? (g_sN + (size_t)tile*TILE_ELEMS)
                                     : (g_qN + (size_t)(tile-NSUP)*TILE_ELEMS);
    for (int idx = t; idx < TILE_ELEMS; idx += 256){
        int row = idx >> 8, col = idx & 255;
        smx[row*PITCH + col] = src[idx];
    }
    __syncthreads();

    const int lane = t & 31, warp = t >> 5;
    const int gid = lane >> 2, tig = lane & 3;
    const int wm = warp >> 2, wn = warp & 3;

    float c[2][8][4];
    #pragma unroll
    for (int mt = 0; mt < 2; mt++)
        #pragma unroll
        for (int nt = 0; nt < 8; nt++)
            #pragma unroll
            for (int i = 0; i < 4; i++) c[mt][nt][i] = 0.f;
    for (int kb = 0; kb < 16; kb++){
        unsigned ah[2][4], al[2][4];
        #pragma unroll
        for (int mt = 0; mt < 2; mt++){
            int r0 = wm*32 + mt*16 + gid;
            int c0 = kb*16 + 2*tig;
            #pragma unroll
            for (int p = 0; p < 4; p++){
                float2 x2 = *(const float2*)(smx + (r0 + (p & 1)*8)*PITCH + c0 + (p >> 1)*8);
                split2(x2.x, x2.y, ah[mt][p], al[mt][p]);
            }
        }
        #pragma unroll
        for (int nt = 0; nt < 8; nt++){
            float4 wv = __ldg(&g_Wm4[((kb*4 + 0)*32 + wn*8 + nt)*32 + lane]);
            unsigned bh[2] = { __float_as_uint(wv.x), __float_as_uint(wv.y) };
            unsigned bl[2] = { __float_as_uint(wv.z), __float_as_uint(wv.w) };
            mma3(c[0][nt], ah[0], al[0], bh, bl);
            mma3(c[1][nt], ah[1], al[1], bh, bl);
        }
    }
    float* dst = g_Y1f + (size_t)tile*TILE_ELEMS;
    #pragma unroll
    for (int mt = 0; mt < 2; mt++){
        int r0 = wm*32 + mt*16 + gid;
        #pragma unroll
        for (int nt = 0; nt < 8; nt++){
            int col = wn*64 + nt*8 + 2*tig;
            *(float2*)(dst + r0*D + col)     = make_float2(c[mt][nt][0], c[mt][nt][1]);
            *(float2*)(dst + (r0+8)*D + col) = make_float2(c[mt][nt][2], c[mt][nt][3]);
        }
    }
}

// ---------------- kernel C2: split Y1 along seq dim -> g_Y1sp[tile][d][kpair] ----------------
__global__ void k_prepY1(){
    int idx = blockIdx.x*256 + threadIdx.x;   // NTILE*8192
    int tile = idx >> 13;
    int rem  = idx & 8191;
    int d  = rem >> 5;
    int kp = rem & 31;
    const float* Y = g_Y1f + (size_t)tile*TILE_ELEMS;
    float y0 = Y[(2*kp)*D + d];
    float y1 = Y[(2*kp+1)*D + d];
    unsigned h, l; split2(y0, y1, h, l);
    g_Y1sp[idx] = make_uint2(h, l);
}

// ---------------- merged attention GEMM: pv (out -> a_t) AND y1 (c2 regs) ----------------
// out[64,256] = A[64,64] * B[64,256];  c2 = A[64,64] @ Y1[64,256] in proj fragment layout
// transA=0: A[m][k] = attm[m*PA + k];  transA=1: A[m][k] = attm[k*PA + m]
__device__ __forceinline__ void attn_pv_y1(const float* __restrict__ attm, int transA,
                                           const float* __restrict__ Btile,
                                           const uint2* __restrict__ y1sp,
                                           const float* __restrict__ rscale,
                                           float* __restrict__ out,
                                           float c2[2][4][4], int t){
    const int lane = t & 31, warp = t >> 5;
    const int gid = lane >> 2, tig = lane & 3;
    const int wm = warp >> 3, wn = warp & 7;
    float c[2][4][4];
    #pragma unroll
    for (int mt = 0; mt < 2; mt++)
        #pragma unroll
        for (int nt = 0; nt < 4; nt++)
            #pragma unroll
            for (int i = 0; i < 4; i++){ c[mt][nt][i] = 0.f; c2[mt][nt][i] = 0.f; }

    for (int kb = 0; kb < 4; kb++){
        // prefetch y1 fragments (L2 LDG) at top of body
        uint2 u0[4], u1[4];
        #pragma unroll
        for (int nt = 0; nt < 4; nt++){
            int d0 = wn*32 + nt*8 + gid;
            int kp = kb*8 + tig;
            u0[nt] = __ldg(&y1sp[d0*32 + kp]);
            u1[nt] = __ldg(&y1sp[d0*32 + kp + 4]);
        }
        // shared A-splits
        unsigned ah[2][4], al[2][4];
        #pragma unroll
        for (int mt = 0; mt < 2; mt++){
            int r0 = wm*32 + mt*16 + gid;
            int c0 = kb*16 + 2*tig;
            #pragma unroll
            for (int p = 0; p < 4; p++){
                int rr = r0 + (p & 1)*8;
                int cc = c0 + (p >> 1)*8;
                float v0, v1;
                if (transA){ v0 = attm[cc*PA + rr]; v1 = attm[(cc+1)*PA + rr]; }
                else { float2 v = *(const float2*)(attm + rr*PA + cc); v0 = v.x; v1 = v.y; }
                split2(v0, v1, ah[mt][p], al[mt][p]);
            }
        }
        // pv mma (B from smem)
        #pragma unroll
        for (int nt = 0; nt < 4; nt++){
            int d0 = wn*32 + nt*8 + gid;
            int k0 = kb*16 + 2*tig;
            unsigned bh[2], bl[2];
            split2(Btile[k0*PITCH + d0],     Btile[(k0+1)*PITCH + d0], bh[0], bl[0]);
            split2(Btile[(k0+8)*PITCH + d0], Btile[(k0+9)*PITCH + d0], bh[1], bl[1]);
            mma3(c[0][nt], ah[0], al[0], bh, bl);
            mma3(c[1][nt], ah[1], al[1], bh, bl);
        }
        // y1 mma (B prefetched)
        #pragma unroll
        for (int nt = 0; nt < 4; nt++){
            unsigned bh[2] = { u0[nt].x, u1[nt].x };
            unsigned bl[2] = { u0[nt].y, u1[nt].y };
            mma3(c2[0][nt], ah[0], al[0], bh, bl);
            mma3(c2[1][nt], ah[1], al[1], bh, bl);
        }
    }
    #pragma unroll
    for (int mt = 0; mt < 2; mt++){
        int r0 = wm*32 + mt*16 + gid;
        float s0 = rscale ? rscale[r0]   : 1.0f;
        float s1 = rscale ? rscale[r0+8] : 1.0f;
        #pragma unroll
        for (int nt = 0; nt < 4; nt++){
            int col = wn*32 + nt*8 + 2*tig;
            *(float2*)(out + r0*PITCH + col)     = make_float2(c[mt][nt][0]*s0, c[mt][nt][1]*s0);
            *(float2*)(out + (r0+8)*PITCH + col) = make_float2(c[mt][nt][2]*s1, c[mt][nt][3]*s1);
            c2[mt][nt][0] *= s0; c2[mt][nt][1] *= s0;
            c2[mt][nt][2] *= s1; c2[mt][nt][3] *= s1;
        }
    }
}

// ---------------- enhanced projection (2 features) + mish + pool + LN (512 threads) ----------
__device__ __forceinline__ void proj_phase(
    const float* __restrict__ xt, const float* __restrict__ at,
    const float4* __restrict__ basef, const float c2[2][4][4],
    float* pmax, float* psum, float* pool_out,
    const float* __restrict__ ln2g, const float* __restrict__ ln2b,
    float* red, int t)
{
    const int lane = t & 31, warp = t >> 5;
    const int gid = lane >> 2, tig = lane & 3;
    const int wm = warp >> 3, wn = warp & 7;

    float c[2][4][4];
    #pragma unroll
    for (int mt = 0; mt < 2; mt++){
        int r16 = wm*2 + mt;
        #pragma unroll
        for (int nt = 0; nt < 4; nt++){
            int j8 = wn*4 + nt;
            float4 v = __ldg(&basef[(r16*32 + j8)*32 + lane]);
            c[mt][nt][0] = v.x + c2[mt][nt][0];
            c[mt][nt][1] = v.y + c2[mt][nt][1];
            c[mt][nt][2] = v.z + c2[mt][nt][2];
            c[mt][nt][3] = v.w + c2[mt][nt][3];
        }
    }

    for (int kb = 0; kb < 16; kb++){
        float2 xv[2][4], av[2][4];
        #pragma unroll
        for (int mt = 0; mt < 2; mt++){
            int r0 = wm*32 + mt*16 + gid;
            int c0 = kb*16 + 2*tig;
            #pragma unroll
            for (int p = 0; p < 4; p++){
                int rr = r0 + (p & 1)*8;
                int cc = c0 + (p >> 1)*8;
                xv[mt][p] = *(const float2*)(xt + rr*PITCH + cc);
                av[mt][p] = *(const float2*)(at + rr*PITCH + cc);
            }
        }
        // feature |x - a|  (weights prefetched for this feature only — register diet)
        {
            float4 wv[4];
            #pragma unroll
            for (int nt = 0; nt < 4; nt++)
                wv[nt] = __ldg(&g_Wm4[((kb*4 + 1)*32 + wn*4 + nt)*32 + lane]);
            unsigned ah[2][4], al[2][4];
            #pragma unroll
            for (int mt = 0; mt < 2; mt++)
                #pragma unroll
                for (int p = 0; p < 4; p++)
                    split2(fabsf(xv[mt][p].x - av[mt][p].x),
                           fabsf(xv[mt][p].y - av[mt][p].y), ah[mt][p], al[mt][p]);
            #pragma unroll
            for (int nt = 0; nt < 4; nt++){
                unsigned bh[2] = { __float_as_uint(wv[nt].x), __float_as_uint(wv[nt].y) };
                unsigned bl[2] = { __float_as_uint(wv[nt].z), __float_as_uint(wv[nt].w) };
                mma3(c[0][nt], ah[0], al[0], bh, bl);
                mma3(c[1][nt], ah[1], al[1], bh, bl);
            }
        }
        // feature x * a
        {
            float4 wv[4];
            #pragma unroll
            for (int nt = 0; nt < 4; nt++)
                wv[nt] = __ldg(&g_Wm4[((kb*4 + 2)*32 + wn*4 + nt)*32 + lane]);
            unsigned ah[2][4], al[2][4];
            #pragma unroll
            for (int mt = 0; mt < 2; mt++)
                #pragma unroll
                for (int p = 0; p < 4; p++)
                    split2(xv[mt][p].x * av[mt][p].x,
                           xv[mt][p].y * av[mt][p].y, ah[mt][p], al[mt][p]);
            #pragma unroll
            for (int nt = 0; nt < 4; nt++){
                unsigned bh[2] = { __float_as_uint(wv[nt].x), __float_as_uint(wv[nt].y) };
                unsigned bl[2] = { __float_as_uint(wv[nt].z), __float_as_uint(wv[nt].w) };
                mma3(c[0][nt], ah[0], al[0], bh, bl);
                mma3(c[1][nt], ah[1], al[1], bh, bl);
            }
        }
    }

    // mish + pooled max/sum; warp owns cols wn*32 + nt*8 + 2tig + e, rows wm*32..+31
    float mymax[4][2], mysum[4][2];
    #pragma unroll
    for (int nt = 0; nt < 4; nt++){
        #pragma unroll
        for (int e = 0; e < 2; e++){
            float v00 = mishf(c[0][nt][e]);
            float v01 = mishf(c[0][nt][2+e]);
            float v10 = mishf(c[1][nt][e]);
            float v11 = mishf(c[1][nt][2+e]);
            float mx = fmaxf(fmaxf(v00, v01), fmaxf(v10, v11));
            float sm = (v00 + v01) + (v10 + v11);
            #pragma unroll
            for (int off = 4; off < 32; off <<= 1){
                mx = fmaxf(mx, __shfl_xor_sync(0xffffffffu, mx, off));
                sm += __shfl_xor_sync(0xffffffffu, sm, off);
            }
            mymax[nt][e] = mx; mysum[nt][e] = sm;
        }
    }
    if (wm == 1 && gid == 0){
        #pragma unroll
        for (int nt = 0; nt < 4; nt++)
            #pragma unroll
            for (int e = 0; e < 2; e++){
                int j = wn*32 + nt*8 + 2*tig + e;
                pmax[j] = mymax[nt][e]; psum[j] = mysum[nt][e];
            }
    }
    __syncthreads();
    if (wm == 0 && gid == 0){
        #pragma unroll
        for (int nt = 0; nt < 4; nt++)
            #pragma unroll
            for (int e = 0; e < 2; e++){
                int j = wn*32 + nt*8 + 2*tig + e;
                pool_out[j]     = fmaxf(mymax[nt][e], pmax[j]);
                pool_out[D + j] = (mysum[nt][e] + psum[j]) * (1.0f/(float)Lh);
            }
    }
    __syncthreads();

    // LayerNorm over 512 (one element per thread)
    float v = pool_out[t];
    float S  = blockSum512(v,   red, t);
    float SS = blockSum512(v*v, red, t);
    float mean = S  * (1.0f/512.0f);
    float var  = SS * (1.0f/512.0f) - mean*mean;
    float inv  = rsqrtf(var + 1e-5f);
    pool_out[t] = (v - mean)*inv*ln2g[t] + ln2b[t];
    __syncthreads();
}

// ---------------- kernel D: one CTA per (query, support) pair (512 threads) ----------------
__global__ void __launch_bounds__(512, 1) k_pair(
    const float* __restrict__ ln2g, const float* __restrict__ ln2b)
{
    extern __shared__ float sm[];
    float* s_t  = sm + SM_S;
    float* q_t  = sm + SM_Q;
    float* a_t  = sm + SM_A;
    float* att  = sm + SM_ATT;
    float* pmax = sm + SM_PMAX;
    float* psum = sm + SM_PSUM;
    float* pool = sm + SM_POOL;
    float* rmax = sm + SM_RMAX;
    float* rsum = sm + SM_RSUM;
    float* cmax = sm + SM_CMAX;
    float* csum = sm + SM_CSUM;
    float* red  = sm + SM_RED;

    const int m = blockIdx.x;
    const int b = m / (NQh*Nh);
    const int rem = m % (NQh*Nh);
    const int iq = rem / Nh;
    const int n  = rem % Nh;
    const int sIdx = b*Nh + n;
    const int qIdx = b*NQh + iq;
    const int qTile = NSUP + qIdx;
    const int t = threadIdx.x;
    const int lane = t & 31, warp = t >> 5;
    const int gid = lane >> 2, tig = lane & 3;

    // load tiles into pitched smem
    {
        const float* sp = g_sN + (size_t)sIdx*TILE_ELEMS;
        const float* qp = g_qN + (size_t)qIdx*TILE_ELEMS;
        for (int idx = t; idx < TILE_ELEMS; idx += 512){
            int row = idx >> 8, col = idx & 255;
            s_t[row*PITCH + col] = sp[idx];
            q_t[row*PITCH + col] = qp[idx];
        }
    }
    __syncthreads();

    // att[l][k] = s[l] . q[k]  (16 warps: 4x4 tiling of 16x16 output tiles)
    {
        const int wma = warp >> 2, wna = warp & 3;
        float ca[2][4];
        #pragma unroll
        for (int nt = 0; nt < 2; nt++)
            #pragma unroll
            for (int i = 0; i < 4; i++) ca[nt][i] = 0.f;
        for (int kb = 0; kb < 16; kb++){
            unsigned ah[4], al[4];
            int r0 = wma*16 + gid;
            int c0 = kb*16 + 2*tig;
            #pragma unroll
            for (int p = 0; p < 4; p++){
                float2 s2 = *(const float2*)(s_t + (r0 + (p & 1)*8)*PITCH + c0 + (p >> 1)*8);
                split2(s2.x, s2.y, ah[p], al[p]);
            }
            #pragma unroll
            for (int nt = 0; nt < 2; nt++){
                int n0 = wna*16 + nt*8 + gid;
                unsigned bh[2], bl[2];
                float2 q0 = *(const float2*)(q_t + n0*PITCH + c0);
                float2 q1 = *(const float2*)(q_t + n0*PITCH + c0 + 8);
                split2(q0.x, q0.y, bh[0], bl[0]);
                split2(q1.x, q1.y, bh[1], bl[1]);
                mma3(ca[nt], ah, al, bh, bl);
            }
        }
        #pragma unroll
        for (int nt = 0; nt < 2; nt++){
            int r0 = wma*16 + gid;
            int col = wna*16 + nt*8 + 2*tig;
            *(float2*)(att + r0*PA + col)     = make_float2(ca[nt][0], ca[nt][1]);
            *(float2*)(att + (r0+8)*PA + col) = make_float2(ca[nt][2], ca[nt][3]);
        }
    }
    __syncthreads();

    // row maxima (512 threads: 8 per row)
    {
        int row = t >> 3, sub = t & 7;
        const float* rp = att + row*PA + sub*8;
        float mx = fmaxf(fmaxf(fmaxf(rp[0], rp[1]), fmaxf(rp[2], rp[3])),
                         fmaxf(fmaxf(rp[4], rp[5]), fmaxf(rp[6], rp[7])));
        #pragma unroll
        for (int o = 1; o < 8; o <<= 1) mx = fmaxf(mx, __shfl_xor_sync(0xffffffffu, mx, o));
        if (sub == 0) rmax[row] = mx;
    }
    // column maxima (8 per column)
    {
        int col = t >> 3, sub = t & 7;
        float mx = -3.4e38f;
        #pragma unroll
        for (int i = 0; i < 8; i++) mx = fmaxf(mx, att[(sub*8 + i)*PA + col]);
        #pragma unroll
        for (int o = 1; o < 8; o <<= 1) mx = fmaxf(mx, __shfl_xor_sync(0xffffffffu, mx, o));
        if (sub == 0) cmax[col] = mx;
    }
    __syncthreads();

    // att := E = exp(att - rmax[l])
    {
        const int k = t & 63, l0 = t >> 6;
        #pragma unroll
        for (int i = 0; i < 8; i++){
            int l = l0 + 8*i;
            att[l*PA + k] = __expf(att[l*PA + k] - rmax[l]);
        }
    }
    __syncthreads();

    // row sums (8 threads per row)
    {
        int row = t >> 3, sub = t & 7;
        const float* rp = att + row*PA + sub*8;
        float s = ((rp[0] + rp[1]) + (rp[2] + rp[3])) + ((rp[4] + rp[5]) + (rp[6] + rp[7]));
        #pragma unroll
        for (int o = 1; o < 8; o <<= 1) s += __shfl_xor_sync(0xffffffffu, s, o);
        if (sub == 0) rsum[row] = 1.0f / s;
    }
    // column sums rebased to cmax (8 threads per column)
    {
        int col = t >> 3, sub = t & 7;
        float cm = cmax[col];
        float s = 0.f;
        #pragma unroll
        for (int i = 0; i < 8; i++){
            int l = sub*8 + i;
            float h = __expf(0.5f*(rmax[l] - cm));   // split to avoid overflow
            s += att[l*PA + col] * h * h;
        }
        #pragma unroll
        for (int o = 1; o < 8; o <<= 1) s += __shfl_xor_sync(0xffffffffu, s, o);
        if (sub == 0) csum[col] = 1.0f / s;
    }
    __syncthreads();

    float c2[2][4][4];
    // s_att = (E @ Q) / rowsum -> a_t;  c2 = rsum-scaled (E @ Y1_q)
    attn_pv_y1(att, 0, q_t, g_Y1sp + (size_t)qTile*8192, rsum, a_t, c2, t);
    __syncthreads();

    // phase S -> pool[512..1023]
    proj_phase(s_t, a_t, g_baseF + (size_t)sIdx*4096, c2,
               pmax, psum, pool + 512, ln2g, ln2b, red, t);

    // att := P_col = exp(att_raw - cmax[k]) / colsum
    {
        const int k = t & 63, l0 = t >> 6;
        float ci = csum[k], cm = cmax[k];
        #pragma unroll
        for (int i = 0; i < 8; i++){
            int l = l0 + 8*i;
            float h = __expf(0.5f*(rmax[l] - cm));
            att[l*PA + k] = att[l*PA + k] * h * h * ci;
        }
    }
    __syncthreads();

    // q_att = P_col^T @ S -> a_t;  c2 = P_col^T @ Y1_s
    attn_pv_y1(att, 1, s_t, g_Y1sp + (size_t)sIdx*8192, (const float*)0, a_t, c2, t);
    __syncthreads();

    // phase Q -> pool[0..511]
    proj_phase(q_t, a_t, g_baseF + (size_t)qTile*4096, c2,
               pmax, psum, pool, ln2g, ln2b, red, t);

    // store pooled cat vector; MLP head handled by k_head
    g_pool[(size_t)m*1024 + t]       = pool[t];
    g_pool[(size_t)m*1024 + 512 + t] = pool[512 + t];
}

// ---------------- kernel H: batched MLP head (8 pairs per block, float4 streams) ----------
__global__ void __launch_bounds__(256) k_head(
    const float* __restrict__ W1,  const float* __restrict__ b1v,
    const float* __restrict__ W2,  const float* __restrict__ b2,
    const float* __restrict__ W3,  const float* __restrict__ b3)
{
    __shared__ float ps[8*1024];
    __shared__ float red[8][8];
    int t = threadIdx.x;
    int m0 = blockIdx.x*8;
    for (int i = t; i < 8*1024; i += 256) ps[i] = g_pool[(size_t)m0*1024 + i];
    __syncthreads();
    float acc[8];
    #pragma unroll
    for (int r = 0; r < 8; r++) acc[r] = 0.f;
    const float4* w4 = (const float4*)(W1 + (size_t)t*1024);   // row t of W1 [256][1024]
    #pragma unroll 2
    for (int c4 = 0; c4 < 256; c4++){
        float4 w = __ldg(&w4[c4]);
        #pragma unroll
        for (int r = 0; r < 8; r++){
            float4 p = *(const float4*)(ps + r*1024 + c4*4);
            acc[r] += p.x*w.x;
            acc[r] += p.y*w.y;
            acc[r] += p.z*w.z;
            acc[r] += p.w*w.w;
        }
    }
    float b1j = b1v[t], w2j = W2[t];
    #pragma unroll
    for (int r = 0; r < 8; r++){
        float part = mishf(acc[r] + b1j) * w2j;
        #pragma unroll
        for (int o = 16; o > 0; o >>= 1) part += __shfl_xor_sync(0xffffffffu, part, o);
        if ((t & 31) == 0) red[r][t >> 5] = part;
    }
    __syncthreads();
    if (t < 8){
        float tot = 0.f;
        #pragma unroll
        for (int w = 0; w < 8; w++) tot += red[t][w];
        g_logits[m0 + t] = mishf(tot + b2[0])*W3[0] + b3[0];
    }
}

// ---------------- kernel E: min-append, logits layout, argmax ----------------
__global__ void k_final(float* __restrict__ out, int out_size){
    int u = threadIdx.x;
    if (u >= Bh*NQh) return;
    float v[Nh];
    float mn = 3.4e38f;
    #pragma unroll
    for (int n2 = 0; n2 < Nh; n2++){
        v[n2] = g_logits[u*Nh + n2];
        mn = fminf(mn, v[n2]);
    }
    if (out_size >= 1100){
        float best = -3.4e38f; int bi = 0;
        #pragma unroll
        for (int n2 = 0; n2 < Nh; n2++){
            out[u*(Nh+1) + n2] = v[n2];
            if (v[n2] > best){ best = v[n2]; bi = n2; }
        }
        out[u*(Nh+1) + Nh] = mn - 1.0f;
        if (out_size >= 1200) out[Bh*NQh*(Nh+1) + u] = (float)bi;
    } else if (out_size == Bh*NQh){
        float best = -3.4e38f; int bi = 0;
        #pragma unroll
        for (int n2 = 0; n2 < Nh; n2++)
            if (v[n2] > best){ best = v[n2]; bi = n2; }
        ((int*)out)[u] = bi;
    }
}

// ---------------- launch ----------------
extern "C" void kernel_launch(void* const* d_in, const int* in_sizes, int n_in,
                              void* d_out, int out_size)
{
    const float* support = (const float*)d_in[0];
    const float* query   = (const float*)d_in[1];
    const float* ln_g    = (const float*)d_in[2];
    const float* ln_b    = (const float*)d_in[3];
    const float* ln2_g   = (const float*)d_in[4];
    const float* ln2_b   = (const float*)d_in[5];
    const float* proj_W  = (const float*)d_in[6];
    const float* proj_b  = (const float*)d_in[7];
    const float* W1      = (const float*)d_in[8];
    const float* b1      = (const float*)d_in[9];
    const float* W2      = (const float*)d_in[10];
    const float* b2      = (const float*)d_in[11];
    const float* W3      = (const float*)d_in[12];
    const float* b3      = (const float*)d_in[13];

    cudaFuncSetAttribute(k_pair,  cudaFuncAttributeMaxDynamicSharedMemorySize, SMEM_PAIR_BYTES);
    cudaFuncSetAttribute(k_base1, cudaFuncAttributeMaxDynamicSharedMemorySize, SMEM_BASE_BYTES);
    cudaFuncSetAttribute(k_base2, cudaFuncAttributeMaxDynamicSharedMemorySize, SMEM_BASE_BYTES);

    k_ln<<<(NSUP + NQRY)*Lh, 256>>>(support, query, ln_g, ln_b);
    k_prepw<<<256, 256>>>(proj_W);
    k_base1<<<NTILE, 256, SMEM_BASE_BYTES>>>(proj_b);
    k_base2<<<NTILE, 256, SMEM_BASE_BYTES>>>();
    k_prepY1<<<NTILE*32, 256>>>();
    k_pair<<<Mh, 512, SMEM_PAIR_BYTES>>>(ln2_g, ln2_b);
    k_head<<<Mh/8, 256>>>(W1, b1, W2, b2, W3, b3);
    k_final<<<1, 128>>>((float*)d_out, out_size);
}

// round 15
// speedup vs baseline: 1.1606x; 1.0066x over previous
#include <cuda_runtime.h>
#include <cstdint>

#define D 256
#define Lh 64
#define Bh 2
#define Nh 10
#define NQh 50
#define Mh 1000
#define NSUP 20
#define NQRY 100
#define NTILE 120
#define PITCH 260
#define PA 68
#define TILE_ELEMS (Lh*D)

// ---------------- scratch (device globals; no allocations allowed) ----------------
__device__ float g_sN[NSUP*TILE_ELEMS];
__device__ float g_qN[NQRY*TILE_ELEMS];
__device__ float4 g_Wm4[16*4*32*32];              // proj_W bf16 hi/lo b-fragments (1MB)
__device__ float4 g_baseF[NTILE*4*32*32];         // base = x@W0^T + b, fragment-native fp32
__device__ float g_Y1f[NTILE*TILE_ELEMS];         // scratch: Y1 = x@W1blk fp32
__device__ uint2 g_Y1sp[NTILE*256*32];            // Y1 split bf16 hi/lo, [tile][d][kpair]
__device__ float g_pool[Mh*1024];                 // pooled+LN'd cat vectors
__device__ float g_logits[Mh];

// Shared-memory layout (floats) for the pair kernel
#define SM_S    0
#define SM_Q    (SM_S + Lh*PITCH)
#define SM_A    (SM_Q + Lh*PITCH)
#define SM_ATT  (SM_A + Lh*PITCH)
#define SM_PMAX (SM_ATT + Lh*PA)
#define SM_PSUM (SM_PMAX + D)
#define SM_POOL (SM_PSUM + D)       // 1024: [0..511]=q_pool, [512..1023]=s_pool
#define SM_RMAX (SM_POOL + 1024)
#define SM_RSUM (SM_RMAX + 64)
#define SM_CMAX (SM_RSUM + 64)
#define SM_CSUM (SM_CMAX + 64)
#define SM_RED  (SM_CSUM + 64)
#define SM_TOTAL (SM_RED + 32)
#define SMEM_PAIR_BYTES (SM_TOTAL*4)
#define SMEM_BASE_BYTES (Lh*PITCH*4)

// ---------------- bf16 split helpers ----------------
__device__ __forceinline__ unsigned pack2(float x0, float x1){
    unsigned r; asm("cvt.rn.bf16x2.f32 %0, %1, %2;" : "=r"(r) : "f"(x1), "f"(x0)); return r;
}
__device__ __forceinline__ void split2(float x0, float x1, unsigned &h, unsigned &l){
    h = pack2(x0, x1);
    float h0 = __uint_as_float(h << 16);
    float h1 = __uint_as_float(h & 0xffff0000u);
    l = pack2(x0 - h0, x1 - h1);
}
__device__ __forceinline__ void mmab(float* c, const unsigned* a, const unsigned* b){
    asm volatile("mma.sync.aligned.m16n8k16.row.col.f32.bf16.bf16.f32 "
        "{%0,%1,%2,%3}, {%4,%5,%6,%7}, {%8,%9}, {%0,%1,%2,%3};\n"
        : "+f"(c[0]), "+f"(c[1]), "+f"(c[2]), "+f"(c[3])
        : "r"(a[0]), "r"(a[1]), "r"(a[2]), "r"(a[3]), "r"(b[0]), "r"(b[1]));
}
// 3-term (full precision): hh + hl + lh
__device__ __forceinline__ void mma3(float* c, const unsigned* ah, const unsigned* al,
                                     const unsigned* bh, const unsigned* bl){
    mmab(c, ah, bh); mmab(c, ah, bl); mmab(c, al, bh);
}

// mish(x) = x * tanh(softplus(x)) = x * (u^2+2u)/(u^2+2u+2), u = e^x
__device__ __forceinline__ float mishf(float x){
    if (x > 20.0f) return x;
    float u = __expf(x);
    float v = u*u + 2.0f*u;
    return x * v / (v + 2.0f);
}

// block-wide sum over 512 threads (16 warps)
__device__ __forceinline__ float blockSum512(float v, float* red, int t){
    #pragma unroll
    for (int o = 16; o > 0; o >>= 1) v += __shfl_xor_sync(0xffffffffu, v, o);
    if ((t & 31) == 0) red[t >> 5] = v;
    __syncthreads();
    float s = 0.f;
    #pragma unroll
    for (int w = 0; w < 16; w++) s += red[w];
    __syncthreads();
    return s;
}

// ---------------- kernel A: row LayerNorm of support & query ----------------
__global__ void k_ln(const float* __restrict__ sup, const float* __restrict__ qry,
                     const float* __restrict__ gg, const float* __restrict__ bb){
    __shared__ float rs[8], rq[8];
    int r = blockIdx.x, t = threadIdx.x;
    const float* src; float* dst;
    const int nsr = NSUP*Lh;
    if (r < nsr){ src = sup + (size_t)r*D; dst = g_sN + (size_t)r*D; }
    else        { src = qry + (size_t)(r-nsr)*D; dst = g_qN + (size_t)(r-nsr)*D; }
    float x = src[t];
    float s = x, q = x*x;
    #pragma unroll
    for (int o = 16; o > 0; o >>= 1){
        s += __shfl_xor_sync(0xffffffffu, s, o);
        q += __shfl_xor_sync(0xffffffffu, q, o);
    }
    if ((t & 31) == 0){ rs[t>>5] = s; rq[t>>5] = q; }
    __syncthreads();
    float S = 0.f, Q2 = 0.f;
    #pragma unroll
    for (int w = 0; w < 8; w++){ S += rs[w]; Q2 += rq[w]; }
    float mu  = S  * (1.0f/D);
    float var = Q2 * (1.0f/D) - mu*mu;
    float inv = rsqrtf(var + 1e-5f);
    dst[t] = (x - mu)*inv*gg[t] + bb[t];
}

// ---------------- kernel B2: proj_W -> bf16 hi/lo b-fragments ----------------
__global__ void k_prepw(const float* __restrict__ pw){
    int idx = blockIdx.x*256 + threadIdx.x;     // 65536 total
    int lane = idx & 31;
    int jt   = (idx >> 5) & 31;
    int w    = (idx >> 10) & 3;
    int kb   = idx >> 12;
    int tig = lane & 3, gid = lane >> 2;
    int j = jt*8 + gid;
    int cblk = (w == 3) ? 0 : (w + 1);
    size_t base = (size_t)j*1024 + cblk*256 + kb*16 + 2*tig;
    unsigned bh0, bl0, bh1, bl1;
    split2(pw[base],     pw[base + 1], bh0, bl0);
    split2(pw[base + 8], pw[base + 9], bh1, bl1);
    g_Wm4[idx] = make_float4(__uint_as_float(bh0), __uint_as_float(bh1),
                             __uint_as_float(bl0), __uint_as_float(bl1));
}

// ---------------- kernel C-a: per-tile base = x @ W0^T + b (3-term, fragment layout) -------
__global__ void __launch_bounds__(256,2) k_base1(const float* __restrict__ pb){
    extern __shared__ float smx[];
    int tile = blockIdx.x, t = threadIdx.x;
    const float* src = (tile < NSUP) ? (g_sN + (size_t)tile*TILE_ELEMS)
                                     : (g_qN + (size_t)(tile-NSUP)*TILE_ELEMS);
    for (int idx = t; idx < TILE_ELEMS; idx += 256){
        int row = idx >> 8, col = idx & 255;
        smx[row*PITCH + col] = src[idx];
    }
    __syncthreads();

    const int lane = t & 31, warp = t >> 5;
    const int gid = lane >> 2, tig = lane & 3;
    const int wm = warp >> 2, wn = warp & 3;

    float c[2][8][4];
    #pragma unroll
    for (int nt = 0; nt < 8; nt++){
        int col = wn*64 + nt*8 + 2*tig;
        float b0 = pb[col], b1 = pb[col+1];
        #pragma unroll
        for (int mt = 0; mt < 2; mt++){
            c[mt][nt][0] = b0; c[mt][nt][1] = b1;
            c[mt][nt][2] = b0; c[mt][nt][3] = b1;
        }
    }
    for (int kb = 0; kb < 16; kb++){
        unsigned ah[2][4], al[2][4];
        #pragma unroll
        for (int mt = 0; mt < 2; mt++){
            int r0 = wm*32 + mt*16 + gid;
            int c0 = kb*16 + 2*tig;
            #pragma unroll
            for (int p = 0; p < 4; p++){
                float2 x2 = *(const float2*)(smx + (r0 + (p & 1)*8)*PITCH + c0 + (p >> 1)*8);
                split2(x2.x, x2.y, ah[mt][p], al[mt][p]);
            }
        }
        #pragma unroll
        for (int nt = 0; nt < 8; nt++){
            float4 wv = __ldg(&g_Wm4[((kb*4 + 3)*32 + wn*8 + nt)*32 + lane]);
            unsigned bh[2] = { __float_as_uint(wv.x), __float_as_uint(wv.y) };
            unsigned bl[2] = { __float_as_uint(wv.z), __float_as_uint(wv.w) };
            mma3(c[0][nt], ah[0], al[0], bh, bl);
            mma3(c[1][nt], ah[1], al[1], bh, bl);
        }
    }
    #pragma unroll
    for (int mt = 0; mt < 2; mt++){
        int r16 = wm*2 + mt;
        #pragma unroll
        for (int nt = 0; nt < 8; nt++){
            int j8 = wn*8 + nt;
            g_baseF[((tile*4 + r16)*32 + j8)*32 + lane] =
                make_float4(c[mt][nt][0], c[mt][nt][1], c[mt][nt][2], c[mt][nt][3]);
        }
    }
}

// ---------------- kernel C-b: per-tile Y1 = x @ W1blk^T (3-term, fp32 scratch) --------------
__global__ void __launch_bounds__(256,2) k_base2(){
    extern __shared__ float smx[];
    int tile = blockIdx.x, t = threadIdx.x;
    const float* src = (tile < NSUP) ? (g_sN + (size_t)tile*TILE_ELEMS)
                                     : (g_qN + (size_t)(tile-NSUP)*TILE_ELEMS);
    for (int idx = t; idx < TILE_ELEMS; idx += 256){
        int row = idx >> 8, col = idx & 255;
        smx[row*PITCH + col] = src[idx];
    }
    __syncthreads();

    const int lane = t & 31, warp = t >> 5;
    const int gid = lane >> 2, tig = lane & 3;
    const int wm = warp >> 2, wn = warp & 3;

    float c[2][8][4];
    #pragma unroll
    for (int mt = 0; mt < 2; mt++)
        #pragma unroll
        for (int nt = 0; nt < 8; nt++)
            #pragma unroll
            for (int i = 0; i < 4; i++) c[mt][nt][i] = 0.f;
    for (int kb = 0; kb < 16; kb++){
        unsigned ah[2][4], al[2][4];
        #pragma unroll
        for (int mt = 0; mt < 2; mt++){
            int r0 = wm*32 + mt*16 + gid;
            int c0 = kb*16 + 2*tig;
            #pragma unroll
            for (int p = 0; p < 4; p++){
                float2 x2 = *(const float2*)(smx + (r0 + (p & 1)*8)*PITCH + c0 + (p >> 1)*8);
                split2(x2.x, x2.y, ah[mt][p], al[mt][p]);
            }
        }
        #pragma unroll
        for (int nt = 0; nt < 8; nt++){
            float4 wv = __ldg(&g_Wm4[((kb*4 + 0)*32 + wn*8 + nt)*32 + lane]);
            unsigned bh[2] = { __float_as_uint(wv.x), __float_as_uint(wv.y) };
            unsigned bl[2] = { __float_as_uint(wv.z), __float_as_uint(wv.w) };
            mma3(c[0][nt], ah[0], al[0], bh, bl);
            mma3(c[1][nt], ah[1], al[1], bh, bl);
        }
    }
    float* dst = g_Y1f + (size_t)tile*TILE_ELEMS;
    #pragma unroll
    for (int mt = 0; mt < 2; mt++){
        int r0 = wm*32 + mt*16 + gid;
        #pragma unroll
        for (int nt = 0; nt < 8; nt++){
            int col = wn*64 + nt*8 + 2*tig;
            *(float2*)(dst + r0*D + col)     = make_float2(c[mt][nt][0], c[mt][nt][1]);
            *(float2*)(dst + (r0+8)*D + col) = make_float2(c[mt][nt][2], c[mt][nt][3]);
        }
    }
}

// ---------------- kernel C2: split Y1 along seq dim -> g_Y1sp[tile][d][kpair] ----------------
__global__ void k_prepY1(){
    int idx = blockIdx.x*256 + threadIdx.x;   // NTILE*8192
    int tile = idx >> 13;
    int rem  = idx & 8191;
    int d  = rem >> 5;
    int kp = rem & 31;
    const float* Y = g_Y1f + (size_t)tile*TILE_ELEMS;
    float y0 = Y[(2*kp)*D + d];
    float y1 = Y[(2*kp+1)*D + d];
    unsigned h, l; split2(y0, y1, h, l);
    g_Y1sp[idx] = make_uint2(h, l);
}

// ---------------- merged attention GEMM: pv (out -> a_t) AND y1 (c2 regs), 3-term ----------
// out[64,256] = A[64,64] * B[64,256];  c2 = A[64,64] @ Y1[64,256] in proj fragment layout
// transA=0: A[m][k] = attm[m*PA + k];  transA=1: A[m][k] = attm[k*PA + m]
__device__ __forceinline__ void attn_pv_y1(const float* __restrict__ attm, int transA,
                                           const float* __restrict__ Btile,
                                           const uint2* __restrict__ y1sp,
                                           const float* __restrict__ rscale,
                                           float* __restrict__ out,
                                           float c2[2][4][4], int t){
    const int lane = t & 31, warp = t >> 5;
    const int gid = lane >> 2, tig = lane & 3;
    const int wm = warp >> 3, wn = warp & 7;
    float c[2][4][4];
    #pragma unroll
    for (int mt = 0; mt < 2; mt++)
        #pragma unroll
        for (int nt = 0; nt < 4; nt++)
            #pragma unroll
            for (int i = 0; i < 4; i++){ c[mt][nt][i] = 0.f; c2[mt][nt][i] = 0.f; }

    for (int kb = 0; kb < 4; kb++){
        // prefetch y1 fragments (L2 LDG) at top of body
        uint2 u0[4], u1[4];
        #pragma unroll
        for (int nt = 0; nt < 4; nt++){
            int d0 = wn*32 + nt*8 + gid;
            int kp = kb*8 + tig;
            u0[nt] = __ldg(&y1sp[d0*32 + kp]);
            u1[nt] = __ldg(&y1sp[d0*32 + kp + 4]);
        }
        // shared A-splits
        unsigned ah[2][4], al[2][4];
        #pragma unroll
        for (int mt = 0; mt < 2; mt++){
            int r0 = wm*32 + mt*16 + gid;
            int c0 = kb*16 + 2*tig;
            #pragma unroll
            for (int p = 0; p < 4; p++){
                int rr = r0 + (p & 1)*8;
                int cc = c0 + (p >> 1)*8;
                float v0, v1;
                if (transA){ v0 = attm[cc*PA + rr]; v1 = attm[(cc+1)*PA + rr]; }
                else { float2 v = *(const float2*)(attm + rr*PA + cc); v0 = v.x; v1 = v.y; }
                split2(v0, v1, ah[mt][p], al[mt][p]);
            }
        }
        // pv mma (B from smem)
        #pragma unroll
        for (int nt = 0; nt < 4; nt++){
            int d0 = wn*32 + nt*8 + gid;
            int k0 = kb*16 + 2*tig;
            unsigned bh[2], bl[2];
            split2(Btile[k0*PITCH + d0],     Btile[(k0+1)*PITCH + d0], bh[0], bl[0]);
            split2(Btile[(k0+8)*PITCH + d0], Btile[(k0+9)*PITCH + d0], bh[1], bl[1]);
            mma3(c[0][nt], ah[0], al[0], bh, bl);
            mma3(c[1][nt], ah[1], al[1], bh, bl);
        }
        // y1 mma (B prefetched)
        #pragma unroll
        for (int nt = 0; nt < 4; nt++){
            unsigned bh[2] = { u0[nt].x, u1[nt].x };
            unsigned bl[2] = { u0[nt].y, u1[nt].y };
            mma3(c2[0][nt], ah[0], al[0], bh, bl);
            mma3(c2[1][nt], ah[1], al[1], bh, bl);
        }
    }
    #pragma unroll
    for (int mt = 0; mt < 2; mt++){
        int r0 = wm*32 + mt*16 + gid;
        float s0 = rscale ? rscale[r0]   : 1.0f;
        float s1 = rscale ? rscale[r0+8] : 1.0f;
        #pragma unroll
        for (int nt = 0; nt < 4; nt++){
            int col = wn*32 + nt*8 + 2*tig;
            *(float2*)(out + r0*PITCH + col)     = make_float2(c[mt][nt][0]*s0, c[mt][nt][1]*s0);
            *(float2*)(out + (r0+8)*PITCH + col) = make_float2(c[mt][nt][2]*s1, c[mt][nt][3]*s1);
            c2[mt][nt][0] *= s0; c2[mt][nt][1] *= s0;
            c2[mt][nt][2] *= s1; c2[mt][nt][3] *= s1;
        }
    }
}

// ---------------- enhanced projection (2 features, 3-term) + mish + pool + LN ---------------
__device__ __forceinline__ void proj_phase(
    const float* __restrict__ xt, const float* __restrict__ at,
    const float4* __restrict__ basef, const float c2[2][4][4],
    float* pmax, float* psum, float* pool_out,
    const float* __restrict__ ln2g, const float* __restrict__ ln2b,
    float* red, int t)
{
    const int lane = t & 31, warp = t >> 5;
    const int gid = lane >> 2, tig = lane & 3;
    const int wm = warp >> 3, wn = warp & 7;

    float c[2][4][4];
    #pragma unroll
    for (int mt = 0; mt < 2; mt++){
        int r16 = wm*2 + mt;
        #pragma unroll
        for (int nt = 0; nt < 4; nt++){
            int j8 = wn*4 + nt;
            float4 v = __ldg(&basef[(r16*32 + j8)*32 + lane]);
            c[mt][nt][0] = v.x + c2[mt][nt][0];
            c[mt][nt][1] = v.y + c2[mt][nt][1];
            c[mt][nt][2] = v.z + c2[mt][nt][2];
            c[mt][nt][3] = v.w + c2[mt][nt][3];
        }
    }

    for (int kb = 0; kb < 16; kb++){
        float2 xv[2][4], av[2][4];
        #pragma unroll
        for (int mt = 0; mt < 2; mt++){
            int r0 = wm*32 + mt*16 + gid;
            int c0 = kb*16 + 2*tig;
            #pragma unroll
            for (int p = 0; p < 4; p++){
                int rr = r0 + (p & 1)*8;
                int cc = c0 + (p >> 1)*8;
                xv[mt][p] = *(const float2*)(xt + rr*PITCH + cc);
                av[mt][p] = *(const float2*)(at + rr*PITCH + cc);
            }
        }
        // feature |x - a|  (weights prefetched for this feature only — register diet)
        {
            float4 wv[4];
            #pragma unroll
            for (int nt = 0; nt < 4; nt++)
                wv[nt] = __ldg(&g_Wm4[((kb*4 + 1)*32 + wn*4 + nt)*32 + lane]);
            unsigned ah[2][4], al[2][4];
            #pragma unroll
            for (int mt = 0; mt < 2; mt++)
                #pragma unroll
                for (int p = 0; p < 4; p++)
                    split2(fabsf(xv[mt][p].x - av[mt][p].x),
                           fabsf(xv[mt][p].y - av[mt][p].y), ah[mt][p], al[mt][p]);
            #pragma unroll
            for (int nt = 0; nt < 4; nt++){
                unsigned bh[2] = { __float_as_uint(wv[nt].x), __float_as_uint(wv[nt].y) };
                unsigned bl[2] = { __float_as_uint(wv[nt].z), __float_as_uint(wv[nt].w) };
                mma3(c[0][nt], ah[0], al[0], bh, bl);
                mma3(c[1][nt], ah[1], al[1], bh, bl);
            }
        }
        // feature x * a
        {
            float4 wv[4];
            #pragma unroll
            for (int nt = 0; nt < 4; nt++)
                wv[nt] = __ldg(&g_Wm4[((kb*4 + 2)*32 + wn*4 + nt)*32 + lane]);
            unsigned ah[2][4], al[2][4];
            #pragma unroll
            for (int mt = 0; mt < 2; mt++)
                #pragma unroll
                for (int p = 0; p < 4; p++)
                    split2(xv[mt][p].x * av[mt][p].x,
                           xv[mt][p].y * av[mt][p].y, ah[mt][p], al[mt][p]);
            #pragma unroll
            for (int nt = 0; nt < 4; nt++){
                unsigned bh[2] = { __float_as_uint(wv[nt].x), __float_as_uint(wv[nt].y) };
                unsigned bl[2] = { __float_as_uint(wv[nt].z), __float_as_uint(wv[nt].w) };
                mma3(c[0][nt], ah[0], al[0], bh, bl);
                mma3(c[1][nt], ah[1], al[1], bh, bl);
            }
        }
    }

    // mish + pooled max/sum; warp owns cols wn*32 + nt*8 + 2tig + e, rows wm*32..+31
    float mymax[4][2], mysum[4][2];
    #pragma unroll
    for (int nt = 0; nt < 4; nt++){
        #pragma unroll
        for (int e = 0; e < 2; e++){
            float v00 = mishf(c[0][nt][e]);
            float v01 = mishf(c[0][nt][2+e]);
            float v10 = mishf(c[1][nt][e]);
            float v11 = mishf(c[1][nt][2+e]);
            float mx = fmaxf(fmaxf(v00, v01), fmaxf(v10, v11));
            float sm = (v00 + v01) + (v10 + v11);
            #pragma unroll
            for (int off = 4; off < 32; off <<= 1){
                mx = fmaxf(mx, __shfl_xor_sync(0xffffffffu, mx, off));
                sm += __shfl_xor_sync(0xffffffffu, sm, off);
            }
            mymax[nt][e] = mx; mysum[nt][e] = sm;
        }
    }
    if (wm == 1 && gid == 0){
        #pragma unroll
        for (int nt = 0; nt < 4; nt++)
            #pragma unroll
            for (int e = 0; e < 2; e++){
                int j = wn*32 + nt*8 + 2*tig + e;
                pmax[j] = mymax[nt][e]; psum[j] = mysum[nt][e];
            }
    }
    __syncthreads();
    if (wm == 0 && gid == 0){
        #pragma unroll
        for (int nt = 0; nt < 4; nt++)
            #pragma unroll
            for (int e = 0; e < 2; e++){
                int j = wn*32 + nt*8 + 2*tig + e;
                pool_out[j]     = fmaxf(mymax[nt][e], pmax[j]);
                pool_out[D + j] = (mysum[nt][e] + psum[j]) * (1.0f/(float)Lh);
            }
    }
    __syncthreads();

    // LayerNorm over 512 (one element per thread)
    float v = pool_out[t];
    float S  = blockSum512(v,   red, t);
    float SS = blockSum512(v*v, red, t);
    float mean = S  * (1.0f/512.0f);
    float var  = SS * (1.0f/512.0f) - mean*mean;
    float inv  = rsqrtf(var + 1e-5f);
    pool_out[t] = (v - mean)*inv*ln2g[t] + ln2b[t];
    __syncthreads();
}

// ---------------- kernel D: one CTA per (query, support) pair (512 threads) ----------------
__global__ void __launch_bounds__(512, 1) k_pair(
    const float* __restrict__ ln2g, const float* __restrict__ ln2b)
{
    extern __shared__ float sm[];
    float* s_t  = sm + SM_S;
    float* q_t  = sm + SM_Q;
    float* a_t  = sm + SM_A;
    float* att  = sm + SM_ATT;
    float* pmax = sm + SM_PMAX;
    float* psum = sm + SM_PSUM;
    float* pool = sm + SM_POOL;
    float* rmax = sm + SM_RMAX;
    float* rsum = sm + SM_RSUM;
    float* cmax = sm + SM_CMAX;
    float* csum = sm + SM_CSUM;
    float* red  = sm + SM_RED;

    const int m = blockIdx.x;
    const int b = m / (NQh*Nh);
    const int rem = m % (NQh*Nh);
    const int iq = rem / Nh;
    const int n  = rem % Nh;
    const int sIdx = b*Nh + n;
    const int qIdx = b*NQh + iq;
    const int qTile = NSUP + qIdx;
    const int t = threadIdx.x;
    const int lane = t & 31, warp = t >> 5;
    const int gid = lane >> 2, tig = lane & 3;

    // load tiles into pitched smem
    {
        const float* sp = g_sN + (size_t)sIdx*TILE_ELEMS;
        const float* qp = g_qN + (size_t)qIdx*TILE_ELEMS;
        for (int idx = t; idx < TILE_ELEMS; idx += 512){
            int row = idx >> 8, col = idx & 255;
            s_t[row*PITCH + col] = sp[idx];
            q_t[row*PITCH + col] = qp[idx];
        }
    }
    __syncthreads();

    // att[l][k] = s[l] . q[k]  (16 warps; full 3-term)
    {
        const int wma = warp >> 2, wna = warp & 3;
        float ca[2][4];
        #pragma unroll
        for (int nt = 0; nt < 2; nt++)
            #pragma unroll
            for (int i = 0; i < 4; i++) ca[nt][i] = 0.f;
        for (int kb = 0; kb < 16; kb++){
            unsigned ah[4], al[4];
            int r0 = wma*16 + gid;
            int c0 = kb*16 + 2*tig;
            #pragma unroll
            for (int p = 0; p < 4; p++){
                float2 s2 = *(const float2*)(s_t + (r0 + (p & 1)*8)*PITCH + c0 + (p >> 1)*8);
                split2(s2.x, s2.y, ah[p], al[p]);
            }
            #pragma unroll
            for (int nt = 0; nt < 2; nt++){
                int n0 = wna*16 + nt*8 + gid;
                unsigned bh[2], bl[2];
                float2 q0 = *(const float2*)(q_t + n0*PITCH + c0);
                float2 q1 = *(const float2*)(q_t + n0*PITCH + c0 + 8);
                split2(q0.x, q0.y, bh[0], bl[0]);
                split2(q1.x, q1.y, bh[1], bl[1]);
                mma3(ca[nt], ah, al, bh, bl);
            }
        }
        #pragma unroll
        for (int nt = 0; nt < 2; nt++){
            int r0 = wma*16 + gid;
            int col = wna*16 + nt*8 + 2*tig;
            *(float2*)(att + r0*PA + col)     = make_float2(ca[nt][0], ca[nt][1]);
            *(float2*)(att + (r0+8)*PA + col) = make_float2(ca[nt][2], ca[nt][3]);
        }
    }
    __syncthreads();

    // FUSED: row maxima (threads 0..255) + column maxima (threads 256..511)
    if (t < 256){
        int row = t >> 2, sub = t & 3;
        const float* rp = att + row*PA + sub*16;
        float mx = -3.4e38f;
        #pragma unroll
        for (int i = 0; i < 16; i++) mx = fmaxf(mx, rp[i]);
        mx = fmaxf(mx, __shfl_xor_sync(0xffffffffu, mx, 1));
        mx = fmaxf(mx, __shfl_xor_sync(0xffffffffu, mx, 2));
        if (sub == 0) rmax[row] = mx;
    } else {
        int u = t - 256;
        int col = u >> 2, sub = u & 3;
        float mx = -3.4e38f;
        #pragma unroll
        for (int i = 0; i < 16; i++) mx = fmaxf(mx, att[(sub*16 + i)*PA + col]);
        mx = fmaxf(mx, __shfl_xor_sync(0xffffffffu, mx, 1));
        mx = fmaxf(mx, __shfl_xor_sync(0xffffffffu, mx, 2));
        if (sub == 0) cmax[col] = mx;
    }
    __syncthreads();

    // att := E = exp(att - rmax[l])
    {
        const int k = t & 63, l0 = t >> 6;
        #pragma unroll
        for (int i = 0; i < 8; i++){
            int l = l0 + 8*i;
            att[l*PA + k] = __expf(att[l*PA + k] - rmax[l]);
        }
    }
    __syncthreads();

    // FUSED: row sums (threads 0..255) + column sums rebased to cmax (threads 256..511)
    if (t < 256){
        int row = t >> 2, sub = t & 3;
        const float* rp = att + row*PA + sub*16;
        float s = 0.f;
        #pragma unroll
        for (int i = 0; i < 16; i++) s += rp[i];
        s += __shfl_xor_sync(0xffffffffu, s, 1);
        s += __shfl_xor_sync(0xffffffffu, s, 2);
        if (sub == 0) rsum[row] = 1.0f / s;
    } else {
        int u = t - 256;
        int col = u >> 2, sub = u & 3;
        float cm = cmax[col];
        float s = 0.f;
        #pragma unroll
        for (int i = 0; i < 16; i++){
            int l = sub*16 + i;
            float h = __expf(0.5f*(rmax[l] - cm));   // split to avoid overflow
            s += att[l*PA + col] * h * h;
        }
        s += __shfl_xor_sync(0xffffffffu, s, 1);
        s += __shfl_xor_sync(0xffffffffu, s, 2);
        if (sub == 0) csum[col] = 1.0f / s;
    }
    __syncthreads();

    float c2[2][4][4];
    // s_att = (E @ Q) / rowsum -> a_t;  c2 = rsum-scaled (E @ Y1_q)
    attn_pv_y1(att, 0, q_t, g_Y1sp + (size_t)qTile*8192, rsum, a_t, c2, t);
    __syncthreads();

    // phase S -> pool[512..1023]
    proj_phase(s_t, a_t, g_baseF + (size_t)sIdx*4096, c2,
               pmax, psum, pool + 512, ln2g, ln2b, red, t);

    // att := P_col = exp(att_raw - cmax[k]) / colsum
    {
        const int k = t & 63, l0 = t >> 6;
        float ci = csum[k], cm = cmax[k];
        #pragma unroll
        for (int i = 0; i < 8; i++){
            int l = l0 + 8*i;
            float h = __expf(0.5f*(rmax[l] - cm));
            att[l*PA + k] = att[l*PA + k] * h * h * ci;
        }
    }
    __syncthreads();

    // q_att = P_col^T @ S -> a_t;  c2 = P_col^T @ Y1_s
    attn_pv_y1(att, 1, s_t, g_Y1sp + (size_t)sIdx*8192, (const float*)0, a_t, c2, t);
    __syncthreads();

    // phase Q -> pool[0..511]
    proj_phase(q_t, a_t, g_baseF + (size_t)qTile*4096, c2,
               pmax, psum, pool, ln2g, ln2b, red, t);

    // store pooled cat vector; MLP head handled by k_head
    g_pool[(size_t)m*1024 + t]       = pool[t];
    g_pool[(size_t)m*1024 + 512 + t] = pool[512 + t];
}

// ---------------- kernel H: batched MLP head (8 pairs per block, float4 streams) ----------
__global__ void __launch_bounds__(256) k_head(
    const float* __restrict__ W1,  const float* __restrict__ b1v,
    const float* __restrict__ W2,  const float* __restrict__ b2,
    const float* __restrict__ W3,  const float* __restrict__ b3)
{
    __shared__ float ps[8*1024];
    __shared__ float red[8][8];
    int t = threadIdx.x;
    int m0 = blockIdx.x*8;
    for (int i = t; i < 8*1024; i += 256) ps[i] = g_pool[(size_t)m0*1024 + i];
    __syncthreads();
    float acc[8];
    #pragma unroll
    for (int r = 0; r < 8; r++) acc[r] = 0.f;
    const float4* w4 = (const float4*)(W1 + (size_t)t*1024);   // row t of W1 [256][1024]
    #pragma unroll 2
    for (int c4 = 0; c4 < 256; c4++){
        float4 w = __ldg(&w4[c4]);
        #pragma unroll
        for (int r = 0; r < 8; r++){
            float4 p = *(const float4*)(ps + r*1024 + c4*4);
            acc[r] += p.x*w.x;
            acc[r] += p.y*w.y;
            acc[r] += p.z*w.z;
            acc[r] += p.w*w.w;
        }
    }
    float b1j = b1v[t], w2j = W2[t];
    #pragma unroll
    for (int r = 0; r < 8; r++){
        float part = mishf(acc[r] + b1j) * w2j;
        #pragma unroll
        for (int o = 16; o > 0; o >>= 1) part += __shfl_xor_sync(0xffffffffu, part, o);
        if ((t & 31) == 0) red[r][t >> 5] = part;
    }
    __syncthreads();
    if (t < 8){
        float tot = 0.f;
        #pragma unroll
        for (int w = 0; w < 8; w++) tot += red[t][w];
        g_logits[m0 + t] = mishf(tot + b2[0])*W3[0] + b3[0];
    }
}

// ---------------- kernel E: min-append, logits layout, argmax ----------------
__global__ void k_final(float* __restrict__ out, int out_size){
    int u = threadIdx.x;
    if (u >= Bh*NQh) return;
    float v[Nh];
    float mn = 3.4e38f;
    #pragma unroll
    for (int n2 = 0; n2 < Nh; n2++){
        v[n2] = g_logits[u*Nh + n2];
        mn = fminf(mn, v[n2]);
    }
    if (out_size >= 1100){
        float best = -3.4e38f; int bi = 0;
        #pragma unroll
        for (int n2 = 0; n2 < Nh; n2++){
            out[u*(Nh+1) + n2] = v[n2];
            if (v[n2] > best){ best = v[n2]; bi = n2; }
        }
        out[u*(Nh+1) + Nh] = mn - 1.0f;
        if (out_size >= 1200) out[Bh*NQh*(Nh+1) + u] = (float)bi;
    } else if (out_size == Bh*NQh){
        float best = -3.4e38f; int bi = 0;
        #pragma unroll
        for (int n2 = 0; n2 < Nh; n2++)
            if (v[n2] > best){ best = v[n2]; bi = n2; }
        ((int*)out)[u] = bi;
    }
}

// ---------------- launch ----------------
extern "C" void kernel_launch(void* const* d_in, const int* in_sizes, int n_in,
                              void* d_out, int out_size)
{
    const float* support = (const float*)d_in[0];
    const float* query   = (const float*)d_in[1];
    const float* ln_g    = (const float*)d_in[2];
    const float* ln_b    = (const float*)d_in[3];
    const float* ln2_g   = (const float*)d_in[4];
    const float* ln2_b   = (const float*)d_in[5];
    const float* proj_W  = (const float*)d_in[6];
    const float* proj_b  = (const float*)d_in[7];
    const float* W1      = (const float*)d_in[8];
    const float* b1      = (const float*)d_in[9];
    const float* W2      = (const float*)d_in[10];
    const float* b2      = (const float*)d_in[11];
    const float* W3      = (const float*)d_in[12];
    const float* b3      = (const float*)d_in[13];

    cudaFuncSetAttribute(k_pair,  cudaFuncAttributeMaxDynamicSharedMemorySize, SMEM_PAIR_BYTES);
    cudaFuncSetAttribute(k_base1, cudaFuncAttributeMaxDynamicSharedMemorySize, SMEM_BASE_BYTES);
    cudaFuncSetAttribute(k_base2, cudaFuncAttributeMaxDynamicSharedMemorySize, SMEM_BASE_BYTES);

    k_ln<<<(NSUP + NQRY)*Lh, 256>>>(support, query, ln_g, ln_b);
    k_prepw<<<256, 256>>>(proj_W);
    k_base1<<<NTILE, 256, SMEM_BASE_BYTES>>>(proj_b);
    k_base2<<<NTILE, 256, SMEM_BASE_BYTES>>>();
    k_prepY1<<<NTILE*32, 256>>>();
    k_pair<<<Mh, 512, SMEM_PAIR_BYTES>>>(ln2_g, ln2_b);
    k_head<<<Mh/8, 256>>>(W1, b1, W2, b2, W3, b3);
    k_final<<<1, 128>>>((float*)d_out, out_size);
}

// round 16
// speedup vs baseline: 1.1797x; 1.0165x over previous
#include <cuda_runtime.h>
#include <cstdint>

#define D 256
#define Lh 64
#define Bh 2
#define Nh 10
#define NQh 50
#define Mh 1000
#define NSUP 20
#define NQRY 100
#define NTILE 120
#define PITCH 260
#define PA 68
#define TILE_ELEMS (Lh*D)

// ---------------- scratch (device globals; no allocations allowed) ----------------
__device__ float g_sN[NSUP*TILE_ELEMS];
__device__ float g_qN[NQRY*TILE_ELEMS];
__device__ float4 g_Wm4[16*4*32*32];              // proj_W bf16 hi/lo b-fragments (1MB)
__device__ float4 g_baseF[NTILE*4*32*32];         // base = x@W0^T + b, fragment-native fp32
__device__ float g_Y1f[NTILE*TILE_ELEMS];         // scratch: Y1 = x@W1blk fp32
__device__ uint2 g_Y1sp[NTILE*256*32];            // Y1 split bf16 hi/lo, [tile][d][kpair]
__device__ uint4 g_AspH[NTILE*4*16*32];           // tile A-fragments (hi) for att GEMM
__device__ uint4 g_AspL[NTILE*4*16*32];           // tile A-fragments (lo)
__device__ uint4 g_BspS[NTILE*8*16*32];           // tile B-fragments (n=seq,k=d) for att GEMM
__device__ float g_pool[Mh*1024];                 // pooled+LN'd cat vectors
__device__ float g_logits[Mh];

// Shared-memory layout (floats) for the pair kernel
#define SM_S    0
#define SM_Q    (SM_S + Lh*PITCH)
#define SM_A    (SM_Q + Lh*PITCH)
#define SM_ATT  (SM_A + Lh*PITCH)
#define SM_PMAX (SM_ATT + Lh*PA)
#define SM_PSUM (SM_PMAX + D)
#define SM_POOL (SM_PSUM + D)       // 1024: [0..511]=q_pool, [512..1023]=s_pool
#define SM_RMAX (SM_POOL + 1024)
#define SM_RSUM (SM_RMAX + 64)
#define SM_CMAX (SM_RSUM + 64)
#define SM_CSUM (SM_CMAX + 64)
#define SM_RED  (SM_CSUM + 64)
#define SM_TOTAL (SM_RED + 32)
#define SMEM_PAIR_BYTES (SM_TOTAL*4)
#define SMEM_BASE_BYTES (Lh*PITCH*4)

// ---------------- bf16 split helpers ----------------
__device__ __forceinline__ unsigned pack2(float x0, float x1){
    unsigned r; asm("cvt.rn.bf16x2.f32 %0, %1, %2;" : "=r"(r) : "f"(x1), "f"(x0)); return r;
}
__device__ __forceinline__ void split2(float x0, float x1, unsigned &h, unsigned &l){
    h = pack2(x0, x1);
    float h0 = __uint_as_float(h << 16);
    float h1 = __uint_as_float(h & 0xffff0000u);
    l = pack2(x0 - h0, x1 - h1);
}
__device__ __forceinline__ void mmab(float* c, const unsigned* a, const unsigned* b){
    asm volatile("mma.sync.aligned.m16n8k16.row.col.f32.bf16.bf16.f32 "
        "{%0,%1,%2,%3}, {%4,%5,%6,%7}, {%8,%9}, {%0,%1,%2,%3};\n"
        : "+f"(c[0]), "+f"(c[1]), "+f"(c[2]), "+f"(c[3])
        : "r"(a[0]), "r"(a[1]), "r"(a[2]), "r"(a[3]), "r"(b[0]), "r"(b[1]));
}
// 3-term (full precision): hh + hl + lh
__device__ __forceinline__ void mma3(float* c, const unsigned* ah, const unsigned* al,
                                     const unsigned* bh, const unsigned* bl){
    mmab(c, ah, bh); mmab(c, ah, bl); mmab(c, al, bh);
}

// mish(x) = x * tanh(softplus(x)) = x * (u^2+2u)/(u^2+2u+2), u = e^x
__device__ __forceinline__ float mishf(float x){
    if (x > 20.0f) return x;
    float u = __expf(x);
    float v = u*u + 2.0f*u;
    return x * v / (v + 2.0f);
}

// block-wide sum over 512 threads (16 warps)
__device__ __forceinline__ float blockSum512(float v, float* red, int t){
    #pragma unroll
    for (int o = 16; o > 0; o >>= 1) v += __shfl_xor_sync(0xffffffffu, v, o);
    if ((t & 31) == 0) red[t >> 5] = v;
    __syncthreads();
    float s = 0.f;
    #pragma unroll
    for (int w = 0; w < 16; w++) s += red[w];
    __syncthreads();
    return s;
}

// ---------------- kernel A: row LayerNorm of support & query ----------------
__global__ void k_ln(const float* __restrict__ sup, const float* __restrict__ qry,
                     const float* __restrict__ gg, const float* __restrict__ bb){
    __shared__ float rs[8], rq[8];
    int r = blockIdx.x, t = threadIdx.x;
    const float* src; float* dst;
    const int nsr = NSUP*Lh;
    if (r < nsr){ src = sup + (size_t)r*D; dst = g_sN + (size_t)r*D; }
    else        { src = qry + (size_t)(r-nsr)*D; dst = g_qN + (size_t)(r-nsr)*D; }
    float x = src[t];
    float s = x, q = x*x;
    #pragma unroll
    for (int o = 16; o > 0; o >>= 1){
        s += __shfl_xor_sync(0xffffffffu, s, o);
        q += __shfl_xor_sync(0xffffffffu, q, o);
    }
    if ((t & 31) == 0){ rs[t>>5] = s; rq[t>>5] = q; }
    __syncthreads();
    float S = 0.f, Q2 = 0.f;
    #pragma unroll
    for (int w = 0; w < 8; w++){ S += rs[w]; Q2 += rq[w]; }
    float mu  = S  * (1.0f/D);
    float var = Q2 * (1.0f/D) - mu*mu;
    float inv = rsqrtf(var + 1e-5f);
    dst[t] = (x - mu)*inv*gg[t] + bb[t];
}

// ---------------- kernel B2: proj_W -> bf16 hi/lo b-fragments ----------------
__global__ void k_prepw(const float* __restrict__ pw){
    int idx = blockIdx.x*256 + threadIdx.x;     // 65536 total
    int lane = idx & 31;
    int jt   = (idx >> 5) & 31;
    int w    = (idx >> 10) & 3;
    int kb   = idx >> 12;
    int tig = lane & 3, gid = lane >> 2;
    int j = jt*8 + gid;
    int cblk = (w == 3) ? 0 : (w + 1);
    size_t base = (size_t)j*1024 + cblk*256 + kb*16 + 2*tig;
    unsigned bh0, bl0, bh1, bl1;
    split2(pw[base],     pw[base + 1], bh0, bl0);
    split2(pw[base + 8], pw[base + 9], bh1, bl1);
    g_Wm4[idx] = make_float4(__uint_as_float(bh0), __uint_as_float(bh1),
                             __uint_as_float(bl0), __uint_as_float(bl1));
}

// ---------------- kernel C (merged): grid 240; tile = bid>>1, pass = bid&1 ----------------
// pass 0: base = x@W0^T + b (fragment layout) + emit A-fragments for att GEMM
// pass 1: Y1 = x@W1blk^T (fp32 scratch)       + emit B-fragments for att GEMM
__global__ void __launch_bounds__(256,2) k_base(const float* __restrict__ pb){
    extern __shared__ float smx[];
    int bid = blockIdx.x;
    int tile = bid >> 1, pass = bid & 1;
    int t = threadIdx.x;
    const float* src = (tile < NSUP) ? (g_sN + (size_t)tile*TILE_ELEMS)
                                     : (g_qN + (size_t)(tile-NSUP)*TILE_ELEMS);
    for (int idx = t; idx < TILE_ELEMS; idx += 256){
        int row = idx >> 8, col = idx & 255;
        smx[row*PITCH + col] = src[idx];
    }
    __syncthreads();

    const int lane = t & 31, warp = t >> 5;
    const int gid = lane >> 2, tig = lane & 3;
    const int wm = warp >> 2, wn = warp & 3;

    if (pass == 0){
        // ---- base = x @ W0^T + b ----
        float c[2][8][4];
        #pragma unroll
        for (int nt = 0; nt < 8; nt++){
            int col = wn*64 + nt*8 + 2*tig;
            float b0 = pb[col], b1 = pb[col+1];
            #pragma unroll
            for (int mt = 0; mt < 2; mt++){
                c[mt][nt][0] = b0; c[mt][nt][1] = b1;
                c[mt][nt][2] = b0; c[mt][nt][3] = b1;
            }
        }
        for (int kb = 0; kb < 16; kb++){
            unsigned ah[2][4], al[2][4];
            #pragma unroll
            for (int mt = 0; mt < 2; mt++){
                int r0 = wm*32 + mt*16 + gid;
                int c0 = kb*16 + 2*tig;
                #pragma unroll
                for (int p = 0; p < 4; p++){
                    float2 x2 = *(const float2*)(smx + (r0 + (p & 1)*8)*PITCH + c0 + (p >> 1)*8);
                    split2(x2.x, x2.y, ah[mt][p], al[mt][p]);
                }
            }
            #pragma unroll
            for (int nt = 0; nt < 8; nt++){
                float4 wv = __ldg(&g_Wm4[((kb*4 + 3)*32 + wn*8 + nt)*32 + lane]);
                unsigned bh[2] = { __float_as_uint(wv.x), __float_as_uint(wv.y) };
                unsigned bl[2] = { __float_as_uint(wv.z), __float_as_uint(wv.w) };
                mma3(c[0][nt], ah[0], al[0], bh, bl);
                mma3(c[1][nt], ah[1], al[1], bh, bl);
            }
        }
        #pragma unroll
        for (int mt = 0; mt < 2; mt++){
            int r16 = wm*2 + mt;
            #pragma unroll
            for (int nt = 0; nt < 8; nt++){
                int j8 = wn*8 + nt;
                g_baseF[((tile*4 + r16)*32 + j8)*32 + lane] =
                    make_float4(c[mt][nt][0], c[mt][nt][1], c[mt][nt][2], c[mt][nt][3]);
            }
        }
        // ---- emit A-fragments: 2048 uint4 pairs per tile, 8 per thread ----
        #pragma unroll
        for (int i = 0; i < 8; i++){
            int e = t + i*256;
            int elane = e & 31;
            int kb = (e >> 5) & 15;
            int ma = e >> 9;
            int egid = elane >> 2, etig = elane & 3;
            unsigned h[4], l[4];
            #pragma unroll
            for (int p = 0; p < 4; p++){
                int row = ma*16 + egid + (p & 1)*8;
                int col = kb*16 + 2*etig + (p >> 1)*8;
                float2 v = *(const float2*)(smx + row*PITCH + col);
                split2(v.x, v.y, h[p], l[p]);
            }
            size_t idx = ((size_t)(tile*4 + ma)*16 + kb)*32 + elane;
            g_AspH[idx] = make_uint4(h[0], h[1], h[2], h[3]);
            g_AspL[idx] = make_uint4(l[0], l[1], l[2], l[3]);
        }
    } else {
        // ---- Y1 = x @ W1blk^T ----
        float c[2][8][4];
        #pragma unroll
        for (int mt = 0; mt < 2; mt++)
            #pragma unroll
            for (int nt = 0; nt < 8; nt++)
                #pragma unroll
                for (int i = 0; i < 4; i++) c[mt][nt][i] = 0.f;
        for (int kb = 0; kb < 16; kb++){
            unsigned ah[2][4], al[2][4];
            #pragma unroll
            for (int mt = 0; mt < 2; mt++){
                int r0 = wm*32 + mt*16 + gid;
                int c0 = kb*16 + 2*tig;
                #pragma unroll
                for (int p = 0; p < 4; p++){
                    float2 x2 = *(const float2*)(smx + (r0 + (p & 1)*8)*PITCH + c0 + (p >> 1)*8);
                    split2(x2.x, x2.y, ah[mt][p], al[mt][p]);
                }
            }
            #pragma unroll
            for (int nt = 0; nt < 8; nt++){
                float4 wv = __ldg(&g_Wm4[((kb*4 + 0)*32 + wn*8 + nt)*32 + lane]);
                unsigned bh[2] = { __float_as_uint(wv.x), __float_as_uint(wv.y) };
                unsigned bl[2] = { __float_as_uint(wv.z), __float_as_uint(wv.w) };
                mma3(c[0][nt], ah[0], al[0], bh, bl);
                mma3(c[1][nt], ah[1], al[1], bh, bl);
            }
        }
        float* dst = g_Y1f + (size_t)tile*TILE_ELEMS;
        #pragma unroll
        for (int mt = 0; mt < 2; mt++){
            int r0 = wm*32 + mt*16 + gid;
            #pragma unroll
            for (int nt = 0; nt < 8; nt++){
                int col = wn*64 + nt*8 + 2*tig;
                *(float2*)(dst + r0*D + col)     = make_float2(c[mt][nt][0], c[mt][nt][1]);
                *(float2*)(dst + (r0+8)*D + col) = make_float2(c[mt][nt][2], c[mt][nt][3]);
            }
        }
        // ---- emit B-fragments: 4096 uint4 per tile, 16 per thread ----
        #pragma unroll
        for (int i = 0; i < 16; i++){
            int e = t + i*256;
            int elane = e & 31;
            int kb = (e >> 5) & 15;
            int n8 = e >> 9;
            int egid = elane >> 2, etig = elane & 3;
            int row = n8*8 + egid;
            int col = kb*16 + 2*etig;
            float2 v0 = *(const float2*)(smx + row*PITCH + col);
            float2 v1 = *(const float2*)(smx + row*PITCH + col + 8);
            unsigned bh0, bl0, bh1, bl1;
            split2(v0.x, v0.y, bh0, bl0);
            split2(v1.x, v1.y, bh1, bl1);
            g_BspS[((size_t)(tile*8 + n8)*16 + kb)*32 + elane] =
                make_uint4(bh0, bh1, bl0, bl1);
        }
    }
}

// ---------------- kernel C2: split Y1 along seq dim -> g_Y1sp[tile][d][kpair] ----------------
__global__ void k_prepY1(){
    int idx = blockIdx.x*256 + threadIdx.x;   // NTILE*8192
    int tile = idx >> 13;
    int rem  = idx & 8191;
    int d  = rem >> 5;
    int kp = rem & 31;
    const float* Y = g_Y1f + (size_t)tile*TILE_ELEMS;
    float y0 = Y[(2*kp)*D + d];
    float y1 = Y[(2*kp+1)*D + d];
    unsigned h, l; split2(y0, y1, h, l);
    g_Y1sp[idx] = make_uint2(h, l);
}

// ---------------- merged attention GEMM: pv (out -> a_t) AND y1 (c2 regs), 3-term ----------
// out[64,256] = A[64,64] * B[64,256];  c2 = A[64,64] @ Y1[64,256] in proj fragment layout
// transA=0: A[m][k] = attm[m*PA + k];  transA=1: A[m][k] = attm[k*PA + m]
__device__ __forceinline__ void attn_pv_y1(const float* __restrict__ attm, int transA,
                                           const float* __restrict__ Btile,
                                           const uint2* __restrict__ y1sp,
                                           const float* __restrict__ rscale,
                                           float* __restrict__ out,
                                           float c2[2][4][4], int t){
    const int lane = t & 31, warp = t >> 5;
    const int gid = lane >> 2, tig = lane & 3;
    const int wm = warp >> 3, wn = warp & 7;
    float c[2][4][4];
    #pragma unroll
    for (int mt = 0; mt < 2; mt++)
        #pragma unroll
        for (int nt = 0; nt < 4; nt++)
            #pragma unroll
            for (int i = 0; i < 4; i++){ c[mt][nt][i] = 0.f; c2[mt][nt][i] = 0.f; }

    for (int kb = 0; kb < 4; kb++){
        // prefetch y1 fragments (L2 LDG) at top of body
        uint2 u0[4], u1[4];
        #pragma unroll
        for (int nt = 0; nt < 4; nt++){
            int d0 = wn*32 + nt*8 + gid;
            int kp = kb*8 + tig;
            u0[nt] = __ldg(&y1sp[d0*32 + kp]);
            u1[nt] = __ldg(&y1sp[d0*32 + kp + 4]);
        }
        // shared A-splits
        unsigned ah[2][4], al[2][4];
        #pragma unroll
        for (int mt = 0; mt < 2; mt++){
            int r0 = wm*32 + mt*16 + gid;
            int c0 = kb*16 + 2*tig;
            #pragma unroll
            for (int p = 0; p < 4; p++){
                int rr = r0 + (p & 1)*8;
                int cc = c0 + (p >> 1)*8;
                float v0, v1;
                if (transA){ v0 = attm[cc*PA + rr]; v1 = attm[(cc+1)*PA + rr]; }
                else { float2 v = *(const float2*)(attm + rr*PA + cc); v0 = v.x; v1 = v.y; }
                split2(v0, v1, ah[mt][p], al[mt][p]);
            }
        }
        // pv mma (B from smem)
        #pragma unroll
        for (int nt = 0; nt < 4; nt++){
            int d0 = wn*32 + nt*8 + gid;
            int k0 = kb*16 + 2*tig;
            unsigned bh[2], bl[2];
            split2(Btile[k0*PITCH + d0],     Btile[(k0+1)*PITCH + d0], bh[0], bl[0]);
            split2(Btile[(k0+8)*PITCH + d0], Btile[(k0+9)*PITCH + d0], bh[1], bl[1]);
            mma3(c[0][nt], ah[0], al[0], bh, bl);
            mma3(c[1][nt], ah[1], al[1], bh, bl);
        }
        // y1 mma (B prefetched)
        #pragma unroll
        for (int nt = 0; nt < 4; nt++){
            unsigned bh[2] = { u0[nt].x, u1[nt].x };
            unsigned bl[2] = { u0[nt].y, u1[nt].y };
            mma3(c2[0][nt], ah[0], al[0], bh, bl);
            mma3(c2[1][nt], ah[1], al[1], bh, bl);
        }
    }
    #pragma unroll
    for (int mt = 0; mt < 2; mt++){
        int r0 = wm*32 + mt*16 + gid;
        float s0 = rscale ? rscale[r0]   : 1.0f;
        float s1 = rscale ? rscale[r0+8] : 1.0f;
        #pragma unroll
        for (int nt = 0; nt < 4; nt++){
            int col = wn*32 + nt*8 + 2*tig;
            *(float2*)(out + r0*PITCH + col)     = make_float2(c[mt][nt][0]*s0, c[mt][nt][1]*s0);
            *(float2*)(out + (r0+8)*PITCH + col) = make_float2(c[mt][nt][2]*s1, c[mt][nt][3]*s1);
            c2[mt][nt][0] *= s0; c2[mt][nt][1] *= s0;
            c2[mt][nt][2] *= s1; c2[mt][nt][3] *= s1;
        }
    }
}

// ---------------- enhanced projection (2 features, 3-term) + mish + pool + LN ---------------
__device__ __forceinline__ void proj_phase(
    const float* __restrict__ xt, const float* __restrict__ at,
    const float4* __restrict__ basef, const float c2[2][4][4],
    float* pmax, float* psum, float* pool_out,
    const float* __restrict__ ln2g, const float* __restrict__ ln2b,
    float* red, int t)
{
    const int lane = t & 31, warp = t >> 5;
    const int gid = lane >> 2, tig = lane & 3;
    const int wm = warp >> 3, wn = warp & 7;

    float c[2][4][4];
    #pragma unroll
    for (int mt = 0; mt < 2; mt++){
        int r16 = wm*2 + mt;
        #pragma unroll
        for (int nt = 0; nt < 4; nt++){
            int j8 = wn*4 + nt;
            float4 v = __ldg(&basef[(r16*32 + j8)*32 + lane]);
            c[mt][nt][0] = v.x + c2[mt][nt][0];
            c[mt][nt][1] = v.y + c2[mt][nt][1];
            c[mt][nt][2] = v.z + c2[mt][nt][2];
            c[mt][nt][3] = v.w + c2[mt][nt][3];
        }
    }

    for (int kb = 0; kb < 16; kb++){
        float2 xv[2][4], av[2][4];
        #pragma unroll
        for (int mt = 0; mt < 2; mt++){
            int r0 = wm*32 + mt*16 + gid;
            int c0 = kb*16 + 2*tig;
            #pragma unroll
            for (int p = 0; p < 4; p++){
                int rr = r0 + (p & 1)*8;
                int cc = c0 + (p >> 1)*8;
                xv[mt][p] = *(const float2*)(xt + rr*PITCH + cc);
                av[mt][p] = *(const float2*)(at + rr*PITCH + cc);
            }
        }
        // feature |x - a|  (weights prefetched for this feature only — register diet)
        {
            float4 wv[4];
            #pragma unroll
            for (int nt = 0; nt < 4; nt++)
                wv[nt] = __ldg(&g_Wm4[((kb*4 + 1)*32 + wn*4 + nt)*32 + lane]);
            unsigned ah[2][4], al[2][4];
            #pragma unroll
            for (int mt = 0; mt < 2; mt++)
                #pragma unroll
                for (int p = 0; p < 4; p++)
                    split2(fabsf(xv[mt][p].x - av[mt][p].x),
                           fabsf(xv[mt][p].y - av[mt][p].y), ah[mt][p], al[mt][p]);
            #pragma unroll
            for (int nt = 0; nt < 4; nt++){
                unsigned bh[2] = { __float_as_uint(wv[nt].x), __float_as_uint(wv[nt].y) };
                unsigned bl[2] = { __float_as_uint(wv[nt].z), __float_as_uint(wv[nt].w) };
                mma3(c[0][nt], ah[0], al[0], bh, bl);
                mma3(c[1][nt], ah[1], al[1], bh, bl);
            }
        }
        // feature x * a
        {
            float4 wv[4];
            #pragma unroll
            for (int nt = 0; nt < 4; nt++)
                wv[nt] = __ldg(&g_Wm4[((kb*4 + 2)*32 + wn*4 + nt)*32 + lane]);
            unsigned ah[2][4], al[2][4];
            #pragma unroll
            for (int mt = 0; mt < 2; mt++)
                #pragma unroll
                for (int p = 0; p < 4; p++)
                    split2(xv[mt][p].x * av[mt][p].x,
                           xv[mt][p].y * av[mt][p].y, ah[mt][p], al[mt][p]);
            #pragma unroll
            for (int nt = 0; nt < 4; nt++){
                unsigned bh[2] = { __float_as_uint(wv[nt].x), __float_as_uint(wv[nt].y) };
                unsigned bl[2] = { __float_as_uint(wv[nt].z), __float_as_uint(wv[nt].w) };
                mma3(c[0][nt], ah[0], al[0], bh, bl);
                mma3(c[1][nt], ah[1], al[1], bh, bl);
            }
        }
    }

    // mish + pooled max/sum; warp owns cols wn*32 + nt*8 + 2tig + e, rows wm*32..+31
    float mymax[4][2], mysum[4][2];
    #pragma unroll
    for (int nt = 0; nt < 4; nt++){
        #pragma unroll
        for (int e = 0; e < 2; e++){
            float v00 = mishf(c[0][nt][e]);
            float v01 = mishf(c[0][nt][2+e]);
            float v10 = mishf(c[1][nt][e]);
            float v11 = mishf(c[1][nt][2+e]);
            float mx = fmaxf(fmaxf(v00, v01), fmaxf(v10, v11));
            float sm = (v00 + v01) + (v10 + v11);
            #pragma unroll
            for (int off = 4; off < 32; off <<= 1){
                mx = fmaxf(mx, __shfl_xor_sync(0xffffffffu, mx, off));
                sm += __shfl_xor_sync(0xffffffffu, sm, off);
            }
            mymax[nt][e] = mx; mysum[nt][e] = sm;
        }
    }
    if (wm == 1 && gid == 0){
        #pragma unroll
        for (int nt = 0; nt < 4; nt++)
            #pragma unroll
            for (int e = 0; e < 2; e++){
                int j = wn*32 + nt*8 + 2*tig + e;
                pmax[j] = mymax[nt][e]; psum[j] = mysum[nt][e];
            }
    }
    __syncthreads();
    if (wm == 0 && gid == 0){
        #pragma unroll
        for (int nt = 0; nt < 4; nt++)
            #pragma unroll
            for (int e = 0; e < 2; e++){
                int j = wn*32 + nt*8 + 2*tig + e;
                pool_out[j]     = fmaxf(mymax[nt][e], pmax[j]);
                pool_out[D + j] = (mysum[nt][e] + psum[j]) * (1.0f/(float)Lh);
            }
    }
    __syncthreads();

    // LayerNorm over 512 (one element per thread)
    float v = pool_out[t];
    float S  = blockSum512(v,   red, t);
    float SS = blockSum512(v*v, red, t);
    float mean = S  * (1.0f/512.0f);
    float var  = SS * (1.0f/512.0f) - mean*mean;
    float inv  = rsqrtf(var + 1e-5f);
    pool_out[t] = (v - mean)*inv*ln2g[t] + ln2b[t];
    __syncthreads();
}

// ---------------- kernel D: one CTA per (query, support) pair (512 threads) ----------------
__global__ void __launch_bounds__(512, 1) k_pair(
    const float* __restrict__ ln2g, const float* __restrict__ ln2b)
{
    extern __shared__ float sm[];
    float* s_t  = sm + SM_S;
    float* q_t  = sm + SM_Q;
    float* a_t  = sm + SM_A;
    float* att  = sm + SM_ATT;
    float* pmax = sm + SM_PMAX;
    float* psum = sm + SM_PSUM;
    float* pool = sm + SM_POOL;
    float* rmax = sm + SM_RMAX;
    float* rsum = sm + SM_RSUM;
    float* cmax = sm + SM_CMAX;
    float* csum = sm + SM_CSUM;
    float* red  = sm + SM_RED;

    const int m = blockIdx.x;
    const int b = m / (NQh*Nh);
    const int rem = m % (NQh*Nh);
    const int iq = rem / Nh;
    const int n  = rem % Nh;
    const int sIdx = b*Nh + n;
    const int qIdx = b*NQh + iq;
    const int qTile = NSUP + qIdx;
    const int t = threadIdx.x;
    const int lane = t & 31, warp = t >> 5;
    const int gid = lane >> 2, tig = lane & 3;

    // load tiles into pitched smem (first smem consumer is pv, after the barrier below)
    {
        const float* sp = g_sN + (size_t)sIdx*TILE_ELEMS;
        const float* qp = g_qN + (size_t)qIdx*TILE_ELEMS;
        for (int idx = t; idx < TILE_ELEMS; idx += 512){
            int row = idx >> 8, col = idx & 255;
            s_t[row*PITCH + col] = sp[idx];
            q_t[row*PITCH + col] = qp[idx];
        }
    }
    // NOTE: no barrier — att GEMM reads only pre-split global fragments

    // att[l][k] = s[l] . q[k]  (16 warps: 4x4 tiling; operands pre-split in L2)
    {
        const int wma = warp >> 2, wna = warp & 3;
        float ca[2][4];
        #pragma unroll
        for (int nt = 0; nt < 2; nt++)
            #pragma unroll
            for (int i = 0; i < 4; i++) ca[nt][i] = 0.f;
        const uint4* aspH = g_AspH + ((size_t)sIdx*4 + wma)*16*32;
        const uint4* aspL = g_AspL + ((size_t)sIdx*4 + wma)*16*32;
        for (int kb = 0; kb < 16; kb++){
            uint4 AH = __ldg(&aspH[kb*32 + lane]);
            uint4 AL = __ldg(&aspL[kb*32 + lane]);
            unsigned ah[4] = { AH.x, AH.y, AH.z, AH.w };
            unsigned al[4] = { AL.x, AL.y, AL.z, AL.w };
            #pragma unroll
            for (int nt = 0; nt < 2; nt++){
                int n8 = wna*2 + nt;
                uint4 B = __ldg(&g_BspS[(((size_t)qTile*8 + n8)*16 + kb)*32 + lane]);
                unsigned bh[2] = { B.x, B.y };
                unsigned bl[2] = { B.z, B.w };
                mma3(ca[nt], ah, al, bh, bl);
            }
        }
        #pragma unroll
        for (int nt = 0; nt < 2; nt++){
            int r0 = wma*16 + gid;
            int col = wna*16 + nt*8 + 2*tig;
            *(float2*)(att + r0*PA + col)     = make_float2(ca[nt][0], ca[nt][1]);
            *(float2*)(att + (r0+8)*PA + col) = make_float2(ca[nt][2], ca[nt][3]);
        }
    }
    __syncthreads();   // covers att writes AND tile smem stores above

    // FUSED: row maxima (threads 0..255) + column maxima (threads 256..511)
    if (t < 256){
        int row = t >> 2, sub = t & 3;
        const float* rp = att + row*PA + sub*16;
        float mx = -3.4e38f;
        #pragma unroll
        for (int i = 0; i < 16; i++) mx = fmaxf(mx, rp[i]);
        mx = fmaxf(mx, __shfl_xor_sync(0xffffffffu, mx, 1));
        mx = fmaxf(mx, __shfl_xor_sync(0xffffffffu, mx, 2));
        if (sub == 0) rmax[row] = mx;
    } else {
        int u = t - 256;
        int col = u >> 2, sub = u & 3;
        float mx = -3.4e38f;
        #pragma unroll
        for (int i = 0; i < 16; i++) mx = fmaxf(mx, att[(sub*16 + i)*PA + col]);
        mx = fmaxf(mx, __shfl_xor_sync(0xffffffffu, mx, 1));
        mx = fmaxf(mx, __shfl_xor_sync(0xffffffffu, mx, 2));
        if (sub == 0) cmax[col] = mx;
    }
    __syncthreads();

    // att := E = exp(att - rmax[l])
    {
        const int k = t & 63, l0 = t >> 6;
        #pragma unroll
        for (int i = 0; i < 8; i++){
            int l = l0 + 8*i;
            att[l*PA + k] = __expf(att[l*PA + k] - rmax[l]);
        }
    }
    __syncthreads();

    // FUSED: row sums (threads 0..255) + column sums rebased to cmax (threads 256..511)
    if (t < 256){
        int row = t >> 2, sub = t & 3;
        const float* rp = att + row*PA + sub*16;
        float s = 0.f;
        #pragma unroll
        for (int i = 0; i < 16; i++) s += rp[i];
        s += __shfl_xor_sync(0xffffffffu, s, 1);
        s += __shfl_xor_sync(0xffffffffu, s, 2);
        if (sub == 0) rsum[row] = 1.0f / s;
    } else {
        int u = t - 256;
        int col = u >> 2, sub = u & 3;
        float cm = cmax[col];
        float s = 0.f;
        #pragma unroll
        for (int i = 0; i < 16; i++){
            int l = sub*16 + i;
            float h = __expf(0.5f*(rmax[l] - cm));   // split to avoid overflow
            s += att[l*PA + col] * h * h;
        }
        s += __shfl_xor_sync(0xffffffffu, s, 1);
        s += __shfl_xor_sync(0xffffffffu, s, 2);
        if (sub == 0) csum[col] = 1.0f / s;
    }
    __syncthreads();

    float c2[2][4][4];
    // s_att = (E @ Q) / rowsum -> a_t;  c2 = rsum-scaled (E @ Y1_q)
    attn_pv_y1(att, 0, q_t, g_Y1sp + (size_t)qTile*8192, rsum, a_t, c2, t);
    __syncthreads();

    // phase S -> pool[512..1023]
    proj_phase(s_t, a_t, g_baseF + (size_t)sIdx*4096, c2,
               pmax, psum, pool + 512, ln2g, ln2b, red, t);

    // att := P_col = exp(att_raw - cmax[k]) / colsum
    {
        const int k = t & 63, l0 = t >> 6;
        float ci = csum[k], cm = cmax[k];
        #pragma unroll
        for (int i = 0; i < 8; i++){
            int l = l0 + 8*i;
            float h = __expf(0.5f*(rmax[l] - cm));
            att[l*PA + k] = att[l*PA + k] * h * h * ci;
        }
    }
    __syncthreads();

    // q_att = P_col^T @ S -> a_t;  c2 = P_col^T @ Y1_s
    attn_pv_y1(att, 1, s_t, g_Y1sp + (size_t)sIdx*8192, (const float*)0, a_t, c2, t);
    __syncthreads();

    // phase Q -> pool[0..511]
    proj_phase(q_t, a_t, g_baseF + (size_t)qTile*4096, c2,
               pmax, psum, pool, ln2g, ln2b, red, t);

    // store pooled cat vector; MLP head handled by k_head
    g_pool[(size_t)m*1024 + t]       = pool[t];
    g_pool[(size_t)m*1024 + 512 + t] = pool[512 + t];
}

// ---------------- kernel H: batched MLP head (8 pairs per block, float4 streams) ----------
__global__ void __launch_bounds__(256) k_head(
    const float* __restrict__ W1,  const float* __restrict__ b1v,
    const float* __restrict__ W2,  const float* __restrict__ b2,
    const float* __restrict__ W3,  const float* __restrict__ b3)
{
    __shared__ float ps[8*1024];
    __shared__ float red[8][8];
    int t = threadIdx.x;
    int m0 = blockIdx.x*8;
    for (int i = t; i < 8*1024; i += 256) ps[i] = g_pool[(size_t)m0*1024 + i];
    __syncthreads();
    float acc[8];
    #pragma unroll
    for (int r = 0; r < 8; r++) acc[r] = 0.f;
    const float4* w4 = (const float4*)(W1 + (size_t)t*1024);   // row t of W1 [256][1024]
    #pragma unroll 2
    for (int c4 = 0; c4 < 256; c4++){
        float4 w = __ldg(&w4[c4]);
        #pragma unroll
        for (int r = 0; r < 8; r++){
            float4 p = *(const float4*)(ps + r*1024 + c4*4);
            acc[r] += p.x*w.x;
            acc[r] += p.y*w.y;
            acc[r] += p.z*w.z;
            acc[r] += p.w*w.w;
        }
    }
    float b1j = b1v[t], w2j = W2[t];
    #pragma unroll
    for (int r = 0; r < 8; r++){
        float part = mishf(acc[r] + b1j) * w2j;
        #pragma unroll
        for (int o = 16; o > 0; o >>= 1) part += __shfl_xor_sync(0xffffffffu, part, o);
        if ((t & 31) == 0) red[r][t >> 5] = part;
    }
    __syncthreads();
    if (t < 8){
        float tot = 0.f;
        #pragma unroll
        for (int w = 0; w < 8; w++) tot += red[t][w];
        g_logits[m0 + t] = mishf(tot + b2[0])*W3[0] + b3[0];
    }
}

// ---------------- kernel E: min-append, logits layout, argmax ----------------
__global__ void k_final(float* __restrict__ out, int out_size){
    int u = threadIdx.x;
    if (u >= Bh*NQh) return;
    float v[Nh];
    float mn = 3.4e38f;
    #pragma unroll
    for (int n2 = 0; n2 < Nh; n2++){
        v[n2] = g_logits[u*Nh + n2];
        mn = fminf(mn, v[n2]);
    }
    if (out_size >= 1100){
        float best = -3.4e38f; int bi = 0;
        #pragma unroll
        for (int n2 = 0; n2 < Nh; n2++){
            out[u*(Nh+1) + n2] = v[n2];
            if (v[n2] > best){ best = v[n2]; bi = n2; }
        }
        out[u*(Nh+1) + Nh] = mn - 1.0f;
        if (out_size >= 1200) out[Bh*NQh*(Nh+1) + u] = (float)bi;
    } else if (out_size == Bh*NQh){
        float best = -3.4e38f; int bi = 0;
        #pragma unroll
        for (int n2 = 0; n2 < Nh; n2++)
            if (v[n2] > best){ best = v[n2]; bi = n2; }
        ((int*)out)[u] = bi;
    }
}

// ---------------- launch ----------------
extern "C" void kernel_launch(void* const* d_in, const int* in_sizes, int n_in,
                              void* d_out, int out_size)
{
    const float* support = (const float*)d_in[0];
    const float* query   = (const float*)d_in[1];
    const float* ln_g    = (const float*)d_in[2];
    const float* ln_b    = (const float*)d_in[3];
    const float* ln2_g   = (const float*)d_in[4];
    const float* ln2_b   = (const float*)d_in[5];
    const float* proj_W  = (const float*)d_in[6];
    const float* proj_b  = (const float*)d_in[7];
    const float* W1      = (const float*)d_in[8];
    const float* b1      = (const float*)d_in[9];
    const float* W2      = (const float*)d_in[10];
    const float* b2      = (const float*)d_in[11];
    const float* W3      = (const float*)d_in[12];
    const float* b3      = (const float*)d_in[13];

    cudaFuncSetAttribute(k_pair, cudaFuncAttributeMaxDynamicSharedMemorySize, SMEM_PAIR_BYTES);
    cudaFuncSetAttribute(k_base, cudaFuncAttributeMaxDynamicSharedMemorySize, SMEM_BASE_BYTES);

    k_ln<<<(NSUP + NQRY)*Lh, 256>>>(support, query, ln_g, ln_b);
    k_prepw<<<256, 256>>>(proj_W);
    k_base<<<2*NTILE, 256, SMEM_BASE_BYTES>>>(proj_b);
    k_prepY1<<<NTILE*32, 256>>>();
    k_pair<<<Mh, 512, SMEM_PAIR_BYTES>>>(ln2_g, ln2_b);
    k_head<<<Mh/8, 256>>>(W1, b1, W2, b2, W3, b3);
    k_final<<<1, 128>>>((float*)d_out, out_size);
}

// round 17
// speedup vs baseline: 1.1840x; 1.0036x over previous
#include <cuda_runtime.h>
#include <cstdint>

#define D 256
#define Lh 64
#define Bh 2
#define Nh 10
#define NQh 50
#define Mh 1000
#define NSUP 20
#define NQRY 100
#define NTILE 120
#define PITCH 260
#define PA 68
#define TILE_ELEMS (Lh*D)

// ---------------- scratch (device globals; no allocations allowed) ----------------
__device__ float g_sN[NSUP*TILE_ELEMS];
__device__ float g_qN[NQRY*TILE_ELEMS];
__device__ float4 g_Wm4[16*4*32*32];              // proj_W bf16 hi/lo b-fragments (1MB)
__device__ float4 g_baseF[NTILE*4*32*32];         // base = x@W0^T + b, fragment-native fp32
__device__ uint2 g_Y1sp[NTILE*256*32];            // Y1 split bf16 hi/lo, [tile][d][kpair]
__device__ uint4 g_AspH[NTILE*4*16*32];           // tile A-fragments (hi) for att GEMM
__device__ uint4 g_AspL[NTILE*4*16*32];           // tile A-fragments (lo)
__device__ uint4 g_BspS[NTILE*8*16*32];           // tile B-fragments (n=seq,k=d) for att GEMM
__device__ float g_pool[Mh*1024];                 // pooled+LN'd cat vectors
__device__ float g_logits[Mh];

// Shared-memory layout (floats) for the pair kernel
#define SM_S    0
#define SM_Q    (SM_S + Lh*PITCH)
#define SM_A    (SM_Q + Lh*PITCH)
#define SM_ATT  (SM_A + Lh*PITCH)
#define SM_PMAX (SM_ATT + Lh*PA)
#define SM_PSUM (SM_PMAX + D)
#define SM_POOL (SM_PSUM + D)       // 1024: [0..511]=q_pool, [512..1023]=s_pool
#define SM_RMAX (SM_POOL + 1024)
#define SM_RSUM (SM_RMAX + 64)
#define SM_CMAX (SM_RSUM + 64)
#define SM_CSUM (SM_CMAX + 64)
#define SM_RED  (SM_CSUM + 64)
#define SM_TOTAL (SM_RED + 32)
#define SMEM_PAIR_BYTES (SM_TOTAL*4)
#define SMEM_BASE_BYTES (Lh*PITCH*4)

// ---------------- bf16 split helpers ----------------
__device__ __forceinline__ unsigned pack2(float x0, float x1){
    unsigned r; asm("cvt.rn.bf16x2.f32 %0, %1, %2;" : "=r"(r) : "f"(x1), "f"(x0)); return r;
}
__device__ __forceinline__ void split2(float x0, float x1, unsigned &h, unsigned &l){
    h = pack2(x0, x1);
    float h0 = __uint_as_float(h << 16);
    float h1 = __uint_as_float(h & 0xffff0000u);
    l = pack2(x0 - h0, x1 - h1);
}
__device__ __forceinline__ void mmab(float* c, const unsigned* a, const unsigned* b){
    asm volatile("mma.sync.aligned.m16n8k16.row.col.f32.bf16.bf16.f32 "
        "{%0,%1,%2,%3}, {%4,%5,%6,%7}, {%8,%9}, {%0,%1,%2,%3};\n"
        : "+f"(c[0]), "+f"(c[1]), "+f"(c[2]), "+f"(c[3])
        : "r"(a[0]), "r"(a[1]), "r"(a[2]), "r"(a[3]), "r"(b[0]), "r"(b[1]));
}
// 3-term (full precision): hh + hl + lh
__device__ __forceinline__ void mma3(float* c, const unsigned* ah, const unsigned* al,
                                     const unsigned* bh, const unsigned* bl){
    mmab(c, ah, bh); mmab(c, ah, bl); mmab(c, al, bh);
}

// mish(x) = x * tanh(softplus(x)) = x * (u^2+2u)/(u^2+2u+2), u = e^x
__device__ __forceinline__ float mishf(float x){
    if (x > 20.0f) return x;
    float u = __expf(x);
    float v = u*u + 2.0f*u;
    return x * v / (v + 2.0f);
}

// block-wide sum over 512 threads (16 warps)
__device__ __forceinline__ float blockSum512(float v, float* red, int t){
    #pragma unroll
    for (int o = 16; o > 0; o >>= 1) v += __shfl_xor_sync(0xffffffffu, v, o);
    if ((t & 31) == 0) red[t >> 5] = v;
    __syncthreads();
    float s = 0.f;
    #pragma unroll
    for (int w = 0; w < 16; w++) s += red[w];
    __syncthreads();
    return s;
}

// ---------------- kernel A: row LayerNorm of support & query ----------------
__global__ void k_ln(const float* __restrict__ sup, const float* __restrict__ qry,
                     const float* __restrict__ gg, const float* __restrict__ bb){
    __shared__ float rs[8], rq[8];
    int r = blockIdx.x, t = threadIdx.x;
    const float* src; float* dst;
    const int nsr = NSUP*Lh;
    if (r < nsr){ src = sup + (size_t)r*D; dst = g_sN + (size_t)r*D; }
    else        { src = qry + (size_t)(r-nsr)*D; dst = g_qN + (size_t)(r-nsr)*D; }
    float x = src[t];
    float s = x, q = x*x;
    #pragma unroll
    for (int o = 16; o > 0; o >>= 1){
        s += __shfl_xor_sync(0xffffffffu, s, o);
        q += __shfl_xor_sync(0xffffffffu, q, o);
    }
    if ((t & 31) == 0){ rs[t>>5] = s; rq[t>>5] = q; }
    __syncthreads();
    float S = 0.f, Q2 = 0.f;
    #pragma unroll
    for (int w = 0; w < 8; w++){ S += rs[w]; Q2 += rq[w]; }
    float mu  = S  * (1.0f/D);
    float var = Q2 * (1.0f/D) - mu*mu;
    float inv = rsqrtf(var + 1e-5f);
    dst[t] = (x - mu)*inv*gg[t] + bb[t];
}

// ---------------- kernel B2: proj_W -> bf16 hi/lo b-fragments ----------------
__global__ void k_prepw(const float* __restrict__ pw){
    int idx = blockIdx.x*256 + threadIdx.x;     // 65536 total
    int lane = idx & 31;
    int jt   = (idx >> 5) & 31;
    int w    = (idx >> 10) & 3;
    int kb   = idx >> 12;
    int tig = lane & 3, gid = lane >> 2;
    int j = jt*8 + gid;
    int cblk = (w == 3) ? 0 : (w + 1);
    size_t base = (size_t)j*1024 + cblk*256 + kb*16 + 2*tig;
    unsigned bh0, bl0, bh1, bl1;
    split2(pw[base],     pw[base + 1], bh0, bl0);
    split2(pw[base + 8], pw[base + 9], bh1, bl1);
    g_Wm4[idx] = make_float4(__uint_as_float(bh0), __uint_as_float(bh1),
                             __uint_as_float(bl0), __uint_as_float(bl1));
}

// ---------------- kernel C (merged): grid 240; tile = bid>>1, pass = bid&1 ----------------
// pass 0: base = x@W0^T + b (fragment layout) + emit A-fragments for att GEMM
// pass 1: Y1 = x@W1blk^T + emit B-fragments + emit Y1sp (via smem, no global scratch)
__global__ void __launch_bounds__(256,2) k_base(const float* __restrict__ pb){
    extern __shared__ float smx[];
    int bid = blockIdx.x;
    int tile = bid >> 1, pass = bid & 1;
    int t = threadIdx.x;
    const float* src = (tile < NSUP) ? (g_sN + (size_t)tile*TILE_ELEMS)
                                     : (g_qN + (size_t)(tile-NSUP)*TILE_ELEMS);
    for (int idx = t; idx < TILE_ELEMS; idx += 256){
        int row = idx >> 8, col = idx & 255;
        smx[row*PITCH + col] = src[idx];
    }
    __syncthreads();

    const int lane = t & 31, warp = t >> 5;
    const int gid = lane >> 2, tig = lane & 3;
    const int wm = warp >> 2, wn = warp & 3;

    if (pass == 0){
        // ---- base = x @ W0^T + b ----
        float c[2][8][4];
        #pragma unroll
        for (int nt = 0; nt < 8; nt++){
            int col = wn*64 + nt*8 + 2*tig;
            float b0 = pb[col], b1 = pb[col+1];
            #pragma unroll
            for (int mt = 0; mt < 2; mt++){
                c[mt][nt][0] = b0; c[mt][nt][1] = b1;
                c[mt][nt][2] = b0; c[mt][nt][3] = b1;
            }
        }
        for (int kb = 0; kb < 16; kb++){
            unsigned ah[2][4], al[2][4];
            #pragma unroll
            for (int mt = 0; mt < 2; mt++){
                int r0 = wm*32 + mt*16 + gid;
                int c0 = kb*16 + 2*tig;
                #pragma unroll
                for (int p = 0; p < 4; p++){
                    float2 x2 = *(const float2*)(smx + (r0 + (p & 1)*8)*PITCH + c0 + (p >> 1)*8);
                    split2(x2.x, x2.y, ah[mt][p], al[mt][p]);
                }
            }
            #pragma unroll
            for (int nt = 0; nt < 8; nt++){
                float4 wv = __ldg(&g_Wm4[((kb*4 + 3)*32 + wn*8 + nt)*32 + lane]);
                unsigned bh[2] = { __float_as_uint(wv.x), __float_as_uint(wv.y) };
                unsigned bl[2] = { __float_as_uint(wv.z), __float_as_uint(wv.w) };
                mma3(c[0][nt], ah[0], al[0], bh, bl);
                mma3(c[1][nt], ah[1], al[1], bh, bl);
            }
        }
        #pragma unroll
        for (int mt = 0; mt < 2; mt++){
            int r16 = wm*2 + mt;
            #pragma unroll
            for (int nt = 0; nt < 8; nt++){
                int j8 = wn*8 + nt;
                g_baseF[((tile*4 + r16)*32 + j8)*32 + lane] =
                    make_float4(c[mt][nt][0], c[mt][nt][1], c[mt][nt][2], c[mt][nt][3]);
            }
        }
        // ---- emit A-fragments: 2048 uint4 pairs per tile, 8 per thread ----
        #pragma unroll
        for (int i = 0; i < 8; i++){
            int e = t + i*256;
            int elane = e & 31;
            int kb = (e >> 5) & 15;
            int ma = e >> 9;
            int egid = elane >> 2, etig = elane & 3;
            unsigned h[4], l[4];
            #pragma unroll
            for (int p = 0; p < 4; p++){
                int row = ma*16 + egid + (p & 1)*8;
                int col = kb*16 + 2*etig + (p >> 1)*8;
                float2 v = *(const float2*)(smx + row*PITCH + col);
                split2(v.x, v.y, h[p], l[p]);
            }
            size_t idx = ((size_t)(tile*4 + ma)*16 + kb)*32 + elane;
            g_AspH[idx] = make_uint4(h[0], h[1], h[2], h[3]);
            g_AspL[idx] = make_uint4(l[0], l[1], l[2], l[3]);
        }
    } else {
        // ---- Y1 = x @ W1blk^T (accumulators in registers) ----
        float c[2][8][4];
        #pragma unroll
        for (int mt = 0; mt < 2; mt++)
            #pragma unroll
            for (int nt = 0; nt < 8; nt++)
                #pragma unroll
                for (int i = 0; i < 4; i++) c[mt][nt][i] = 0.f;
        for (int kb = 0; kb < 16; kb++){
            unsigned ah[2][4], al[2][4];
            #pragma unroll
            for (int mt = 0; mt < 2; mt++){
                int r0 = wm*32 + mt*16 + gid;
                int c0 = kb*16 + 2*tig;
                #pragma unroll
                for (int p = 0; p < 4; p++){
                    float2 x2 = *(const float2*)(smx + (r0 + (p & 1)*8)*PITCH + c0 + (p >> 1)*8);
                    split2(x2.x, x2.y, ah[mt][p], al[mt][p]);
                }
            }
            #pragma unroll
            for (int nt = 0; nt < 8; nt++){
                float4 wv = __ldg(&g_Wm4[((kb*4 + 0)*32 + wn*8 + nt)*32 + lane]);
                unsigned bh[2] = { __float_as_uint(wv.x), __float_as_uint(wv.y) };
                unsigned bl[2] = { __float_as_uint(wv.z), __float_as_uint(wv.w) };
                mma3(c[0][nt], ah[0], al[0], bh, bl);
                mma3(c[1][nt], ah[1], al[1], bh, bl);
            }
        }
        // ---- emit B-fragments FIRST (reads x tile in smem): 16 per thread ----
        #pragma unroll
        for (int i = 0; i < 16; i++){
            int e = t + i*256;
            int elane = e & 31;
            int kb = (e >> 5) & 15;
            int n8 = e >> 9;
            int egid = elane >> 2, etig = elane & 3;
            int row = n8*8 + egid;
            int col = kb*16 + 2*etig;
            float2 v0 = *(const float2*)(smx + row*PITCH + col);
            float2 v1 = *(const float2*)(smx + row*PITCH + col + 8);
            unsigned bh0, bl0, bh1, bl1;
            split2(v0.x, v0.y, bh0, bl0);
            split2(v1.x, v1.y, bh1, bl1);
            g_BspS[((size_t)(tile*8 + n8)*16 + kb)*32 + elane] =
                make_uint4(bh0, bh1, bl0, bl1);
        }
        __syncthreads();   // all x-tile reads (mma + B emit) complete before overwrite

        // ---- store Y1 into smem (overwriting x tile) ----
        #pragma unroll
        for (int mt = 0; mt < 2; mt++){
            int r0 = wm*32 + mt*16 + gid;
            #pragma unroll
            for (int nt = 0; nt < 8; nt++){
                int col = wn*64 + nt*8 + 2*tig;
                *(float2*)(smx + r0*PITCH + col)     = make_float2(c[mt][nt][0], c[mt][nt][1]);
                *(float2*)(smx + (r0+8)*PITCH + col) = make_float2(c[mt][nt][2], c[mt][nt][3]);
            }
        }
        __syncthreads();

        // ---- emit Y1sp[tile][d][kpair] from smem: 8192 uint2, 32 per thread ----
        // e = kp*256 + d  ->  d = e & 255 = t (conflict-free LDS, coalesced STG)
        uint2* dst = g_Y1sp + (size_t)tile*8192;
        #pragma unroll
        for (int kp = 0; kp < 32; kp++){
            float y0 = smx[(2*kp)*PITCH + t];
            float y1 = smx[(2*kp + 1)*PITCH + t];
            unsigned h, l; split2(y0, y1, h, l);
            dst[t*32 + kp] = make_uint2(h, l);
        }
    }
}

// ---------------- merged attention GEMM: pv (out -> a_t) AND y1 (c2 regs), 3-term ----------
// out[64,256] = A[64,64] * B[64,256];  c2 = A[64,64] @ Y1[64,256] in proj fragment layout
// transA=0: A[m][k] = attm[m*PA + k];  transA=1: A[m][k] = attm[k*PA + m]
__device__ __forceinline__ void attn_pv_y1(const float* __restrict__ attm, int transA,
                                           const float* __restrict__ Btile,
                                           const uint2* __restrict__ y1sp,
                                           const float* __restrict__ rscale,
                                           float* __restrict__ out,
                                           float c2[2][4][4], int t){
    const int lane = t & 31, warp = t >> 5;
    const int gid = lane >> 2, tig = lane & 3;
    const int wm = warp >> 3, wn = warp & 7;
    float c[2][4][4];
    #pragma unroll
    for (int mt = 0; mt < 2; mt++)
        #pragma unroll
        for (int nt = 0; nt < 4; nt++)
            #pragma unroll
            for (int i = 0; i < 4; i++){ c[mt][nt][i] = 0.f; c2[mt][nt][i] = 0.f; }

    for (int kb = 0; kb < 4; kb++){
        // prefetch y1 fragments (L2 LDG) at top of body
        uint2 u0[4], u1[4];
        #pragma unroll
        for (int nt = 0; nt < 4; nt++){
            int d0 = wn*32 + nt*8 + gid;
            int kp = kb*8 + tig;
            u0[nt] = __ldg(&y1sp[d0*32 + kp]);
            u1[nt] = __ldg(&y1sp[d0*32 + kp + 4]);
        }
        // shared A-splits
        unsigned ah[2][4], al[2][4];
        #pragma unroll
        for (int mt = 0; mt < 2; mt++){
            int r0 = wm*32 + mt*16 + gid;
            int c0 = kb*16 + 2*tig;
            #pragma unroll
            for (int p = 0; p < 4; p++){
                int rr = r0 + (p & 1)*8;
                int cc = c0 + (p >> 1)*8;
                float v0, v1;
                if (transA){ v0 = attm[cc*PA + rr]; v1 = attm[(cc+1)*PA + rr]; }
                else { float2 v = *(const float2*)(attm + rr*PA + cc); v0 = v.x; v1 = v.y; }
                split2(v0, v1, ah[mt][p], al[mt][p]);
            }
        }
        // pv mma (B from smem)
        #pragma unroll
        for (int nt = 0; nt < 4; nt++){
            int d0 = wn*32 + nt*8 + gid;
            int k0 = kb*16 + 2*tig;
            unsigned bh[2], bl[2];
            split2(Btile[k0*PITCH + d0],     Btile[(k0+1)*PITCH + d0], bh[0], bl[0]);
            split2(Btile[(k0+8)*PITCH + d0], Btile[(k0+9)*PITCH + d0], bh[1], bl[1]);
            mma3(c[0][nt], ah[0], al[0], bh, bl);
            mma3(c[1][nt], ah[1], al[1], bh, bl);
        }
        // y1 mma (B prefetched)
        #pragma unroll
        for (int nt = 0; nt < 4; nt++){
            unsigned bh[2] = { u0[nt].x, u1[nt].x };
            unsigned bl[2] = { u0[nt].y, u1[nt].y };
            mma3(c2[0][nt], ah[0], al[0], bh, bl);
            mma3(c2[1][nt], ah[1], al[1], bh, bl);
        }
    }
    #pragma unroll
    for (int mt = 0; mt < 2; mt++){
        int r0 = wm*32 + mt*16 + gid;
        float s0 = rscale ? rscale[r0]   : 1.0f;
        float s1 = rscale ? rscale[r0+8] : 1.0f;
        #pragma unroll
        for (int nt = 0; nt < 4; nt++){
            int col = wn*32 + nt*8 + 2*tig;
            *(float2*)(out + r0*PITCH + col)     = make_float2(c[mt][nt][0]*s0, c[mt][nt][1]*s0);
            *(float2*)(out + (r0+8)*PITCH + col) = make_float2(c[mt][nt][2]*s1, c[mt][nt][3]*s1);
            c2[mt][nt][0] *= s0; c2[mt][nt][1] *= s0;
            c2[mt][nt][2] *= s1; c2[mt][nt][3] *= s1;
        }
    }
}

// ---------------- enhanced projection (2 features, 3-term) + mish + pool + LN ---------------
__device__ __forceinline__ void proj_phase(
    const float* __restrict__ xt, const float* __restrict__ at,
    const float4* __restrict__ basef, const float c2[2][4][4],
    float* pmax, float* psum, float* pool_out,
    const float* __restrict__ ln2g, const float* __restrict__ ln2b,
    float* red, int t)
{
    const int lane = t & 31, warp = t >> 5;
    const int gid = lane >> 2, tig = lane & 3;
    const int wm = warp >> 3, wn = warp & 7;

    float c[2][4][4];
    #pragma unroll
    for (int mt = 0; mt < 2; mt++){
        int r16 = wm*2 + mt;
        #pragma unroll
        for (int nt = 0; nt < 4; nt++){
            int j8 = wn*4 + nt;
            float4 v = __ldg(&basef[(r16*32 + j8)*32 + lane]);
            c[mt][nt][0] = v.x + c2[mt][nt][0];
            c[mt][nt][1] = v.y + c2[mt][nt][1];
            c[mt][nt][2] = v.z + c2[mt][nt][2];
            c[mt][nt][3] = v.w + c2[mt][nt][3];
        }
    }

    for (int kb = 0; kb < 16; kb++){
        float2 xv[2][4], av[2][4];
        #pragma unroll
        for (int mt = 0; mt < 2; mt++){
            int r0 = wm*32 + mt*16 + gid;
            int c0 = kb*16 + 2*tig;
            #pragma unroll
            for (int p = 0; p < 4; p++){
                int rr = r0 + (p & 1)*8;
                int cc = c0 + (p >> 1)*8;
                xv[mt][p] = *(const float2*)(xt + rr*PITCH + cc);
                av[mt][p] = *(const float2*)(at + rr*PITCH + cc);
            }
        }
        // feature |x - a|  (weights prefetched for this feature only — register diet)
        {
            float4 wv[4];
            #pragma unroll
            for (int nt = 0; nt < 4; nt++)
                wv[nt] = __ldg(&g_Wm4[((kb*4 + 1)*32 + wn*4 + nt)*32 + lane]);
            unsigned ah[2][4], al[2][4];
            #pragma unroll
            for (int mt = 0; mt < 2; mt++)
                #pragma unroll
                for (int p = 0; p < 4; p++)
                    split2(fabsf(xv[mt][p].x - av[mt][p].x),
                           fabsf(xv[mt][p].y - av[mt][p].y), ah[mt][p], al[mt][p]);
            #pragma unroll
            for (int nt = 0; nt < 4; nt++){
                unsigned bh[2] = { __float_as_uint(wv[nt].x), __float_as_uint(wv[nt].y) };
                unsigned bl[2] = { __float_as_uint(wv[nt].z), __float_as_uint(wv[nt].w) };
                mma3(c[0][nt], ah[0], al[0], bh, bl);
                mma3(c[1][nt], ah[1], al[1], bh, bl);
            }
        }
        // feature x * a
        {
            float4 wv[4];
            #pragma unroll
            for (int nt = 0; nt < 4; nt++)
                wv[nt] = __ldg(&g_Wm4[((kb*4 + 2)*32 + wn*4 + nt)*32 + lane]);
            unsigned ah[2][4], al[2][4];
            #pragma unroll
            for (int mt = 0; mt < 2; mt++)
                #pragma unroll
                for (int p = 0; p < 4; p++)
                    split2(xv[mt][p].x * av[mt][p].x,
                           xv[mt][p].y * av[mt][p].y, ah[mt][p], al[mt][p]);
            #pragma unroll
            for (int nt = 0; nt < 4; nt++){
                unsigned bh[2] = { __float_as_uint(wv[nt].x), __float_as_uint(wv[nt].y) };
                unsigned bl[2] = { __float_as_uint(wv[nt].z), __float_as_uint(wv[nt].w) };
                mma3(c[0][nt], ah[0], al[0], bh, bl);
                mma3(c[1][nt], ah[1], al[1], bh, bl);
            }
        }
    }

    // mish + pooled max/sum; warp owns cols wn*32 + nt*8 + 2tig + e, rows wm*32..+31
    float mymax[4][2], mysum[4][2];
    #pragma unroll
    for (int nt = 0; nt < 4; nt++){
        #pragma unroll
        for (int e = 0; e < 2; e++){
            float v00 = mishf(c[0][nt][e]);
            float v01 = mishf(c[0][nt][2+e]);
            float v10 = mishf(c[1][nt][e]);
            float v11 = mishf(c[1][nt][2+e]);
            float mx = fmaxf(fmaxf(v00, v01), fmaxf(v10, v11));
            float sm = (v00 + v01) + (v10 + v11);
            #pragma unroll
            for (int off = 4; off < 32; off <<= 1){
                mx = fmaxf(mx, __shfl_xor_sync(0xffffffffu, mx, off));
                sm += __shfl_xor_sync(0xffffffffu, sm, off);
            }
            mymax[nt][e] = mx; mysum[nt][e] = sm;
        }
    }
    if (wm == 1 && gid == 0){
        #pragma unroll
        for (int nt = 0; nt < 4; nt++)
            #pragma unroll
            for (int e = 0; e < 2; e++){
                int j = wn*32 + nt*8 + 2*tig + e;
                pmax[j] = mymax[nt][e]; psum[j] = mysum[nt][e];
            }
    }
    __syncthreads();
    if (wm == 0 && gid == 0){
        #pragma unroll
        for (int nt = 0; nt < 4; nt++)
            #pragma unroll
            for (int e = 0; e < 2; e++){
                int j = wn*32 + nt*8 + 2*tig + e;
                pool_out[j]     = fmaxf(mymax[nt][e], pmax[j]);
                pool_out[D + j] = (mysum[nt][e] + psum[j]) * (1.0f/(float)Lh);
            }
    }
    __syncthreads();

    // LayerNorm over 512 (one element per thread)
    float v = pool_out[t];
    float S  = blockSum512(v,   red, t);
    float SS = blockSum512(v*v, red, t);
    float mean = S  * (1.0f/512.0f);
    float var  = SS * (1.0f/512.0f) - mean*mean;
    float inv  = rsqrtf(var + 1e-5f);
    pool_out[t] = (v - mean)*inv*ln2g[t] + ln2b[t];
    __syncthreads();
}

// ---------------- kernel D: one CTA per (query, support) pair (512 threads) ----------------
__global__ void __launch_bounds__(512, 1) k_pair(
    const float* __restrict__ ln2g, const float* __restrict__ ln2b)
{
    extern __shared__ float sm[];
    float* s_t  = sm + SM_S;
    float* q_t  = sm + SM_Q;
    float* a_t  = sm + SM_A;
    float* att  = sm + SM_ATT;
    float* pmax = sm + SM_PMAX;
    float* psum = sm + SM_PSUM;
    float* pool = sm + SM_POOL;
    float* rmax = sm + SM_RMAX;
    float* rsum = sm + SM_RSUM;
    float* cmax = sm + SM_CMAX;
    float* csum = sm + SM_CSUM;
    float* red  = sm + SM_RED;

    const int m = blockIdx.x;
    const int b = m / (NQh*Nh);
    const int rem = m % (NQh*Nh);
    const int iq = rem / Nh;
    const int n  = rem % Nh;
    const int sIdx = b*Nh + n;
    const int qIdx = b*NQh + iq;
    const int qTile = NSUP + qIdx;
    const int t = threadIdx.x;
    const int lane = t & 31, warp = t >> 5;
    const int gid = lane >> 2, tig = lane & 3;

    // load tiles into pitched smem (first smem consumer is pv, after the barrier below)
    {
        const float* sp = g_sN + (size_t)sIdx*TILE_ELEMS;
        const float* qp = g_qN + (size_t)qIdx*TILE_ELEMS;
        for (int idx = t; idx < TILE_ELEMS; idx += 512){
            int row = idx >> 8, col = idx & 255;
            s_t[row*PITCH + col] = sp[idx];
            q_t[row*PITCH + col] = qp[idx];
        }
    }
    // NOTE: no barrier — att GEMM reads only pre-split global fragments

    // att[l][k] = s[l] . q[k]  (16 warps: 4x4 tiling; operands pre-split in L2)
    {
        const int wma = warp >> 2, wna = warp & 3;
        float ca[2][4];
        #pragma unroll
        for (int nt = 0; nt < 2; nt++)
            #pragma unroll
            for (int i = 0; i < 4; i++) ca[nt][i] = 0.f;
        const uint4* aspH = g_AspH + ((size_t)sIdx*4 + wma)*16*32;
        const uint4* aspL = g_AspL + ((size_t)sIdx*4 + wma)*16*32;
        for (int kb = 0; kb < 16; kb++){
            uint4 AH = __ldg(&aspH[kb*32 + lane]);
            uint4 AL = __ldg(&aspL[kb*32 + lane]);
            unsigned ah[4] = { AH.x, AH.y, AH.z, AH.w };
            unsigned al[4] = { AL.x, AL.y, AL.z, AL.w };
            #pragma unroll
            for (int nt = 0; nt < 2; nt++){
                int n8 = wna*2 + nt;
                uint4 B = __ldg(&g_BspS[(((size_t)qTile*8 + n8)*16 + kb)*32 + lane]);
                unsigned bh[2] = { B.x, B.y };
                unsigned bl[2] = { B.z, B.w };
                mma3(ca[nt], ah, al, bh, bl);
            }
        }
        #pragma unroll
        for (int nt = 0; nt < 2; nt++){
            int r0 = wma*16 + gid;
            int col = wna*16 + nt*8 + 2*tig;
            *(float2*)(att + r0*PA + col)     = make_float2(ca[nt][0], ca[nt][1]);
            *(float2*)(att + (r0+8)*PA + col) = make_float2(ca[nt][2], ca[nt][3]);
        }
    }
    __syncthreads();   // covers att writes AND tile smem stores above

    // FUSED: row maxima (threads 0..255) + column maxima (threads 256..511)
    if (t < 256){
        int row = t >> 2, sub = t & 3;
        const float* rp = att + row*PA + sub*16;
        float mx = -3.4e38f;
        #pragma unroll
        for (int i = 0; i < 16; i++) mx = fmaxf(mx, rp[i]);
        mx = fmaxf(mx, __shfl_xor_sync(0xffffffffu, mx, 1));
        mx = fmaxf(mx, __shfl_xor_sync(0xffffffffu, mx, 2));
        if (sub == 0) rmax[row] = mx;
    } else {
        int u = t - 256;
        int col = u >> 2, sub = u & 3;
        float mx = -3.4e38f;
        #pragma unroll
        for (int i = 0; i < 16; i++) mx = fmaxf(mx, att[(sub*16 + i)*PA + col]);
        mx = fmaxf(mx, __shfl_xor_sync(0xffffffffu, mx, 1));
        mx = fmaxf(mx, __shfl_xor_sync(0xffffffffu, mx, 2));
        if (sub == 0) cmax[col] = mx;
    }
    __syncthreads();

    // att := E = exp(att - rmax[l])
    {
        const int k = t & 63, l0 = t >> 6;
        #pragma unroll
        for (int i = 0; i < 8; i++){
            int l = l0 + 8*i;
            att[l*PA + k] = __expf(att[l*PA + k] - rmax[l]);
        }
    }
    __syncthreads();

    // FUSED: row sums (threads 0..255) + column sums rebased to cmax (threads 256..511)
    if (t < 256){
        int row = t >> 2, sub = t & 3;
        const float* rp = att + row*PA + sub*16;
        float s = 0.f;
        #pragma unroll
        for (int i = 0; i < 16; i++) s += rp[i];
        s += __shfl_xor_sync(0xffffffffu, s, 1);
        s += __shfl_xor_sync(0xffffffffu, s, 2);
        if (sub == 0) rsum[row] = 1.0f / s;
    } else {
        int u = t - 256;
        int col = u >> 2, sub = u & 3;
        float cm = cmax[col];
        float s = 0.f;
        #pragma unroll
        for (int i = 0; i < 16; i++){
            int l = sub*16 + i;
            float h = __expf(0.5f*(rmax[l] - cm));   // split to avoid overflow
            s += att[l*PA + col] * h * h;
        }
        s += __shfl_xor_sync(0xffffffffu, s, 1);
        s += __shfl_xor_sync(0xffffffffu, s, 2);
        if (sub == 0) csum[col] = 1.0f / s;
    }
    __syncthreads();

    float c2[2][4][4];
    // s_att = (E @ Q) / rowsum -> a_t;  c2 = rsum-scaled (E @ Y1_q)
    attn_pv_y1(att, 0, q_t, g_Y1sp + (size_t)qTile*8192, rsum, a_t, c2, t);
    __syncthreads();

    // phase S -> pool[512..1023]
    proj_phase(s_t, a_t, g_baseF + (size_t)sIdx*4096, c2,
               pmax, psum, pool + 512, ln2g, ln2b, red, t);

    // att := P_col = exp(att_raw - cmax[k]) / colsum
    {
        const int k = t & 63, l0 = t >> 6;
        float ci = csum[k], cm = cmax[k];
        #pragma unroll
        for (int i = 0; i < 8; i++){
            int l = l0 + 8*i;
            float h = __expf(0.5f*(rmax[l] - cm));
            att[l*PA + k] = att[l*PA + k] * h * h * ci;
        }
    }
    __syncthreads();

    // q_att = P_col^T @ S -> a_t;  c2 = P_col^T @ Y1_s
    attn_pv_y1(att, 1, s_t, g_Y1sp + (size_t)sIdx*8192, (const float*)0, a_t, c2, t);
    __syncthreads();

    // phase Q -> pool[0..511]
    proj_phase(q_t, a_t, g_baseF + (size_t)qTile*4096, c2,
               pmax, psum, pool, ln2g, ln2b, red, t);

    // store pooled cat vector; MLP head handled by k_head
    g_pool[(size_t)m*1024 + t]       = pool[t];
    g_pool[(size_t)m*1024 + 512 + t] = pool[512 + t];
}

// ---------------- kernel H: batched MLP head (8 pairs per block, float4 streams) ----------
__global__ void __launch_bounds__(256) k_head(
    const float* __restrict__ W1,  const float* __restrict__ b1v,
    const float* __restrict__ W2,  const float* __restrict__ b2,
    const float* __restrict__ W3,  const float* __restrict__ b3)
{
    __shared__ float ps[8*1024];
    __shared__ float red[8][8];
    int t = threadIdx.x;
    int m0 = blockIdx.x*8;
    for (int i = t; i < 8*1024; i += 256) ps[i] = g_pool[(size_t)m0*1024 + i];
    __syncthreads();
    float acc[8];
    #pragma unroll
    for (int r = 0; r < 8; r++) acc[r] = 0.f;
    const float4* w4 = (const float4*)(W1 + (size_t)t*1024);   // row t of W1 [256][1024]
    #pragma unroll 2
    for (int c4 = 0; c4 < 256; c4++){
        float4 w = __ldg(&w4[c4]);
        #pragma unroll
        for (int r = 0; r < 8; r++){
            float4 p = *(const float4*)(ps + r*1024 + c4*4);
            acc[r] += p.x*w.x;
            acc[r] += p.y*w.y;
            acc[r] += p.z*w.z;
            acc[r] += p.w*w.w;
        }
    }
    float b1j = b1v[t], w2j = W2[t];
    #pragma unroll
    for (int r = 0; r < 8; r++){
        float part = mishf(acc[r] + b1j) * w2j;
        #pragma unroll
        for (int o = 16; o > 0; o >>= 1) part += __shfl_xor_sync(0xffffffffu, part, o);
        if ((t & 31) == 0) red[r][t >> 5] = part;
    }
    __syncthreads();
    if (t < 8){
        float tot = 0.f;
        #pragma unroll
        for (int w = 0; w < 8; w++) tot += red[t][w];
        g_logits[m0 + t] = mishf(tot + b2[0])*W3[0] + b3[0];
    }
}

// ---------------- kernel E: min-append, logits layout, argmax ----------------
__global__ void k_final(float* __restrict__ out, int out_size){
    int u = threadIdx.x;
    if (u >= Bh*NQh) return;
    float v[Nh];
    float mn = 3.4e38f;
    #pragma unroll
    for (int n2 = 0; n2 < Nh; n2++){
        v[n2] = g_logits[u*Nh + n2];
        mn = fminf(mn, v[n2]);
    }
    if (out_size >= 1100){
        float best = -3.4e38f; int bi = 0;
        #pragma unroll
        for (int n2 = 0; n2 < Nh; n2++){
            out[u*(Nh+1) + n2] = v[n2];
            if (v[n2] > best){ best = v[n2]; bi = n2; }
        }
        out[u*(Nh+1) + Nh] = mn - 1.0f;
        if (out_size >= 1200) out[Bh*NQh*(Nh+1) + u] = (float)bi;
    } else if (out_size == Bh*NQh){
        float best = -3.4e38f; int bi = 0;
        #pragma unroll
        for (int n2 = 0; n2 < Nh; n2++)
            if (v[n2] > best){ best = v[n2]; bi = n2; }
        ((int*)out)[u] = bi;
    }
}

// ---------------- launch ----------------
extern "C" void kernel_launch(void* const* d_in, const int* in_sizes, int n_in,
                              void* d_out, int out_size)
{
    const float* support = (const float*)d_in[0];
    const float* query   = (const float*)d_in[1];
    const float* ln_g    = (const float*)d_in[2];
    const float* ln_b    = (const float*)d_in[3];
    const float* ln2_g   = (const float*)d_in[4];
    const float* ln2_b   = (const float*)d_in[5];
    const float* proj_W  = (const float*)d_in[6];
    const float* proj_b  = (const float*)d_in[7];
    const float* W1      = (const float*)d_in[8];
    const float* b1      = (const float*)d_in[9];
    const float* W2      = (const float*)d_in[10];
    const float* b2      = (const float*)d_in[11];
    const float* W3      = (const float*)d_in[12];
    const float* b3      = (const float*)d_in[13];

    cudaFuncSetAttribute(k_pair, cudaFuncAttributeMaxDynamicSharedMemorySize, SMEM_PAIR_BYTES);
    cudaFuncSetAttribute(k_base, cudaFuncAttributeMaxDynamicSharedMemorySize, SMEM_BASE_BYTES);

    k_ln<<<(NSUP + NQRY)*Lh, 256>>>(support, query, ln_g, ln_b);
    k_prepw<<<256, 256>>>(proj_W);
    k_base<<<2*NTILE, 256, SMEM_BASE_BYTES>>>(proj_b);
    k_pair<<<Mh, 512, SMEM_PAIR_BYTES>>>(ln2_g, ln2_b);
    k_head<<<Mh/8, 256>>>(W1, b1, W2, b2, W3, b3);
    k_final<<<1, 128>>>((float*)d_out, out_size);
}